// round 13
// baseline (speedup 1.0000x reference)
#include <cuda_runtime.h>
#include <cuda_bf16.h>
#include <cstdint>

#define B_  16
#define T_  512
#define V_  8192
#define E_  512
#define H_  1024
#define FH  4096
#define NBLK 128
#define NCB (V_/128)        // 64 column-blocks for logits

// ---------------- device scratch ----------------
__device__ __nv_bfloat16 d_xhi[B_*T_*E_], d_xlo[B_*T_*E_];
__device__ __nv_bfloat16 d_wxnThi[(size_t)FH*E_], d_wxnTlo[(size_t)FH*E_];
__device__ __nv_bfloat16 d_wmxnThi[H_*E_], d_wmxnTlo[H_*E_];
__device__ __nv_bfloat16 d_pwhi[(size_t)V_*H_], d_pwlo[(size_t)V_*H_];
__device__ __nv_bfloat16 d_hshi[B_*T_*H_], d_hslo[B_*T_*H_];
__device__ float d_whnT[(size_t)FH*H_];
__device__ float d_wmhnT[H_*H_];
__device__ float d_nwx[FH], d_nwh[FH], d_nwmx[H_], d_nwmh[H_];
__device__ float d_zx[(size_t)B_*T_*FH];
__device__ float d_mx[B_*T_*H_];
__device__ __nv_bfloat16 d_hhi[B_*H_], d_hlo[B_*H_];
__device__ __nv_bfloat16 d_mthi[B_*H_], d_mtlo[B_*H_];
__device__ float d_pmax[(size_t)B_*T_*NCB];
__device__ float d_psum[(size_t)B_*T_*NCB];
__device__ float d_tlogit[B_*T_];
__device__ float d_rownll[B_*T_];
__device__ unsigned g_hcnt[16 * 8];    // 32B-stride group counters (h ready)
__device__ unsigned g_mcnt[16 * 8];    // 32B-stride group counters (m ready)

// ---------------- helpers ----------------
__device__ __forceinline__ uint32_t smem_u32(const void* p) {
    uint32_t a;
    asm("{ .reg .u64 t; cvta.to.shared.u64 t, %1; cvt.u32.u64 %0, t; }" : "=r"(a) : "l"(p));
    return a;
}
__device__ __forceinline__ void ldm_x4(uint32_t* r, uint32_t addr) {
    asm volatile("ldmatrix.sync.aligned.m8n8.x4.shared.b16 {%0,%1,%2,%3}, [%4];"
                 : "=r"(r[0]), "=r"(r[1]), "=r"(r[2]), "=r"(r[3]) : "r"(addr));
}
__device__ __forceinline__ void ldm_x2(uint32_t* r, uint32_t addr) {
    asm volatile("ldmatrix.sync.aligned.m8n8.x2.shared.b16 {%0,%1}, [%2];"
                 : "=r"(r[0]), "=r"(r[1]) : "r"(addr));
}
__device__ __forceinline__ void mma_bf16(float* c, const uint32_t* a, const uint32_t* b) {
    asm volatile("mma.sync.aligned.m16n8k16.row.col.f32.bf16.bf16.f32 "
                 "{%0,%1,%2,%3}, {%4,%5,%6,%7}, {%8,%9}, {%0,%1,%2,%3};"
                 : "+f"(c[0]), "+f"(c[1]), "+f"(c[2]), "+f"(c[3])
                 : "r"(a[0]), "r"(a[1]), "r"(a[2]), "r"(a[3]), "r"(b[0]), "r"(b[1]));
}
__device__ __forceinline__ uint32_t pk(__nv_bfloat16 a, __nv_bfloat16 b) {
    __nv_bfloat162 t = __halves2bfloat162(a, b);
    return *(uint32_t*)&t;
}
__device__ __forceinline__ void cpa16(uint32_t saddr, const void* g) {
    asm volatile("cp.async.cg.shared.global [%0], [%1], 16;" :: "r"(saddr), "l"(g) : "memory");
}
// per-warp producer-group wait: lane 0 polls, warp syncs (acquire chains via syncwarp)
__device__ __forceinline__ void wait_cnt(const unsigned* p, unsigned target) {
    if ((threadIdx.x & 31) == 0) {
        unsigned v;
        do {
            asm volatile("ld.acquire.gpu.global.u32 %0, [%1];" : "=r"(v) : "l"(p) : "memory");
        } while (v < target);
    }
    __syncwarp();
}

// ---------------- weight norm ----------------
__global__ void zero_norms_kernel() {
    int i = blockIdx.x * 256 + threadIdx.x;
    if (i < FH) { d_nwx[i] = 0.f; d_nwh[i] = 0.f; }
    if (i < H_) { d_nwmx[i] = 0.f; d_nwmh[i] = 0.f; }
}
__global__ void sumsq_kernel(const float* __restrict__ w, float* __restrict__ nrm,
                             int K, int N) {
    int j = blockIdx.x * 256 + threadIdx.x;
    int k0 = blockIdx.y * 32;
    float ss = 0.f;
    #pragma unroll 4
    for (int k = k0; k < k0 + 32; k++) { float v = w[(size_t)k*N + j]; ss += v*v; }
    atomicAdd(&nrm[j], ss);
}
__global__ void scaleT_kernel(const float* __restrict__ w, const float* __restrict__ g,
                              const float* __restrict__ nrm, float* __restrict__ out,
                              int K, int N) {
    __shared__ float tile[32][33];
    int n0 = blockIdx.x * 32, k0 = blockIdx.y * 32;
    int tx = threadIdx.x, ty = threadIdx.y;
    for (int r = ty; r < 32; r += 8)
        tile[r][tx] = w[(size_t)(k0 + r)*N + n0 + tx];
    __syncthreads();
    for (int r = ty; r < 32; r += 8) {
        int n = n0 + r;
        float s = g[n] / fmaxf(sqrtf(nrm[n]), 1e-12f);
        out[(size_t)n*K + k0 + tx] = tile[tx][r] * s;
    }
}
__global__ void scaleT_bf16_kernel(const float* __restrict__ w, const float* __restrict__ g,
                                   const float* __restrict__ nrm,
                                   __nv_bfloat16* __restrict__ ohi,
                                   __nv_bfloat16* __restrict__ olo,
                                   int K, int N) {
    __shared__ float tile[32][33];
    int n0 = blockIdx.x * 32, k0 = blockIdx.y * 32;
    int tx = threadIdx.x, ty = threadIdx.y;
    for (int r = ty; r < 32; r += 8)
        tile[r][tx] = w[(size_t)(k0 + r)*N + n0 + tx];
    __syncthreads();
    for (int r = ty; r < 32; r += 8) {
        int n = n0 + r;
        float s = g[n] / fmaxf(sqrtf(nrm[n]), 1e-12f);
        float v = tile[tx][r] * s;
        __nv_bfloat16 hi = __float2bfloat16(v);
        ohi[(size_t)n*K + k0 + tx] = hi;
        olo[(size_t)n*K + k0 + tx] = __float2bfloat16(v - __bfloat162float(hi));
    }
}
__global__ void split_kernel(const float* __restrict__ w,
                             __nv_bfloat16* __restrict__ ohi,
                             __nv_bfloat16* __restrict__ olo, size_t total) {
    size_t i = (size_t)blockIdx.x * 256 + threadIdx.x;
    if (i >= total) return;
    float v = w[i];
    __nv_bfloat16 hi = __float2bfloat16(v);
    ohi[i] = hi;
    olo[i] = __float2bfloat16(v - __bfloat162float(hi));
}

// ---------------- embedding ----------------
__global__ void embed_kernel(const int* __restrict__ xs, const float* __restrict__ ew,
                             __nv_bfloat16* __restrict__ xhi, __nv_bfloat16* __restrict__ xlo) {
    int r = blockIdx.x;
    int idx = xs[r];
    const float4* src = (const float4*)(ew + (size_t)idx * E_);
    float4 v = src[threadIdx.x];
    if (idx == 0) v = make_float4(0.f, 0.f, 0.f, 0.f);
    size_t base = (size_t)r * E_ + threadIdx.x * 4;
    float vv[4] = {v.x, v.y, v.z, v.w};
    #pragma unroll
    for (int u = 0; u < 4; u++) {
        __nv_bfloat16 hi = __float2bfloat16(vv[u]);
        xhi[base + u] = hi;
        xlo[base + u] = __float2bfloat16(vv[u] - __bfloat162float(hi));
    }
}

// ---------------- mma.sync split-bf16 GEMM cores (unchanged from R12) ----------------
#define GSMEM 131072

__device__ __forceinline__ void gemm_main3(
    char* smem, uint32_t sbase,
    const __nv_bfloat16* Ahi, const __nv_bfloat16* Alo,
    const __nv_bfloat16* Bhi, const __nv_bfloat16* Blo,
    int bm, int bn, int K, float acc[4][4][4])
{
    const int tid = threadIdx.x, lid = tid & 31, wid = tid >> 5;
    const int wm = (wid & 1) * 64, wn = (wid >> 1) * 32;
    #pragma unroll
    for (int mt = 0; mt < 4; mt++)
        #pragma unroll
        for (int nt = 0; nt < 4; nt++)
            #pragma unroll
            for (int u = 0; u < 4; u++) acc[mt][nt][u] = 0.f;

    auto issue = [&](int ch, int buf) {
        int k0 = ch << 6;
        #pragma unroll
        for (int p = 0; p < 16; p++) {
            int i = tid + p * 256;
            int tile = i >> 10, j = i & 1023;
            int row = j >> 3, c = j & 7;
            const __nv_bfloat16* src = (tile == 0) ? Ahi : (tile == 1) ? Alo
                                     : (tile == 2) ? Bhi : Blo;
            int grow = ((tile < 2) ? bm : bn) + row;
            uint32_t sa = sbase + (uint32_t)buf*65536 + tile*16384
                        + (row * 8 + (c ^ (row & 7))) * 16;
            cpa16(sa, src + (size_t)grow * K + k0 + c * 8);
        }
        asm volatile("cp.async.commit_group;" ::: "memory");
    };

    const int nchunk = K >> 6;
    issue(0, 0);
    for (int ch = 0; ch < nchunk; ch++) {
        if (ch + 1 < nchunk) {
            issue(ch + 1, (ch + 1) & 1);
            asm volatile("cp.async.wait_group 1;" ::: "memory");
        } else {
            asm volatile("cp.async.wait_group 0;" ::: "memory");
        }
        __syncthreads();
        const uint32_t boff = sbase + (uint32_t)((ch & 1) * 65536);
        #pragma unroll
        for (int ks = 0; ks < 4; ks++) {
            uint32_t bh[4][2], bl[4][2];
            {
                int row = wn + (lid & 7);
                int cc = 2 * ks + ((lid >> 3) & 1);
                #pragma unroll
                for (int nt = 0; nt < 4; nt++) {
                    int r = row + nt * 8;
                    uint32_t addr = boff + 32768 + (r * 8 + (cc ^ (r & 7))) * 16;
                    ldm_x2(bh[nt], addr);
                    ldm_x2(bl[nt], addr + 16384);
                }
            }
            #pragma unroll
            for (int mt = 0; mt < 4; mt++) {
                int r = wm + mt * 16 + (lid & 7) + ((lid >> 3) & 1) * 8;
                int cc = 2 * ks + (lid >> 4);
                uint32_t addr = boff + (r * 8 + (cc ^ (r & 7))) * 16;
                uint32_t ah[4], al[4];
                ldm_x4(ah, addr);
                ldm_x4(al, addr + 16384);
                #pragma unroll
                for (int nt = 0; nt < 4; nt++) {
                    mma_bf16(acc[mt][nt], ah, bh[nt]);
                    mma_bf16(acc[mt][nt], ah, bl[nt]);
                    mma_bf16(acc[mt][nt], al, bh[nt]);
                }
            }
        }
        __syncthreads();
    }
}

__device__ __forceinline__ void gemm_main1(
    char* smem, uint32_t sbase,
    const __nv_bfloat16* Ahi, const __nv_bfloat16* Bhi,
    int bm, int bn, int K, float acc[4][4][4])
{
    const int tid = threadIdx.x, lid = tid & 31, wid = tid >> 5;
    const int wm = (wid & 1) * 64, wn = (wid >> 1) * 32;
    #pragma unroll
    for (int mt = 0; mt < 4; mt++)
        #pragma unroll
        for (int nt = 0; nt < 4; nt++)
            #pragma unroll
            for (int u = 0; u < 4; u++) acc[mt][nt][u] = 0.f;

    auto issue = [&](int ch, int buf) {
        int k0 = ch << 6;
        #pragma unroll
        for (int p = 0; p < 8; p++) {
            int i = tid + p * 256;
            int tile = i >> 10, j = i & 1023;
            int row = j >> 3, c = j & 7;
            const __nv_bfloat16* src = (tile == 0) ? Ahi : Bhi;
            int grow = ((tile == 0) ? bm : bn) + row;
            uint32_t sa = sbase + (uint32_t)buf*32768 + tile*16384
                        + (row * 8 + (c ^ (row & 7))) * 16;
            cpa16(sa, src + (size_t)grow * K + k0 + c * 8);
        }
        asm volatile("cp.async.commit_group;" ::: "memory");
    };

    const int nchunk = K >> 6;
    issue(0, 0);
    for (int ch = 0; ch < nchunk; ch++) {
        if (ch + 1 < nchunk) {
            issue(ch + 1, (ch + 1) & 1);
            asm volatile("cp.async.wait_group 1;" ::: "memory");
        } else {
            asm volatile("cp.async.wait_group 0;" ::: "memory");
        }
        __syncthreads();
        const uint32_t boff = sbase + (uint32_t)((ch & 1) * 32768);
        #pragma unroll
        for (int ks = 0; ks < 4; ks++) {
            uint32_t bh[4][2];
            {
                int row = wn + (lid & 7);
                int cc = 2 * ks + ((lid >> 3) & 1);
                #pragma unroll
                for (int nt = 0; nt < 4; nt++) {
                    int r = row + nt * 8;
                    ldm_x2(bh[nt], boff + 16384 + (r * 8 + (cc ^ (r & 7))) * 16);
                }
            }
            #pragma unroll
            for (int mt = 0; mt < 4; mt++) {
                int r = wm + mt * 16 + (lid & 7) + ((lid >> 3) & 1) * 8;
                int cc = 2 * ks + (lid >> 4);
                uint32_t ah[4];
                ldm_x4(ah, boff + (r * 8 + (cc ^ (r & 7))) * 16);
                #pragma unroll
                for (int nt = 0; nt < 4; nt++)
                    mma_bf16(acc[mt][nt], ah, bh[nt]);
            }
        }
        __syncthreads();
    }
}

template<bool BIAS>
__global__ void __launch_bounds__(256) mma_gemm(
    const __nv_bfloat16* __restrict__ Ahi, const __nv_bfloat16* __restrict__ Alo,
    const __nv_bfloat16* __restrict__ Bhi, const __nv_bfloat16* __restrict__ Blo,
    const float* __restrict__ bias, float* __restrict__ C,
    int M, int N, int K)
{
    extern __shared__ char smem[];
    const uint32_t sbase = smem_u32(smem);
    const int tid = threadIdx.x, lid = tid & 31, wid = tid >> 5;
    const int wm = (wid & 1) * 64, wn = (wid >> 1) * 32;
    const int bn = blockIdx.x * 128, bm = blockIdx.y * 128;
    float acc[4][4][4];
    gemm_main3(smem, sbase, Ahi, Alo, Bhi, Blo, bm, bn, K, acc);

    const int mrow = (lid >> 2), ncol = (lid & 3) * 2;
    #pragma unroll
    for (int mt = 0; mt < 4; mt++) {
        #pragma unroll
        for (int nt = 0; nt < 4; nt++) {
            int row0 = bm + wm + mt * 16 + mrow;
            int col = bn + wn + nt * 8 + ncol;
            float2 v0 = make_float2(acc[mt][nt][0], acc[mt][nt][1]);
            float2 v1 = make_float2(acc[mt][nt][2], acc[mt][nt][3]);
            if (BIAS) {
                float b0 = bias[col], b1 = bias[col + 1];
                v0.x += b0; v0.y += b1;
                v1.x += b0; v1.y += b1;
            }
            *(float2*)&C[(size_t)row0 * N + col] = v0;
            *(float2*)&C[(size_t)(row0 + 8) * N + col] = v1;
        }
    }
}

// ---------------- fused logits (1-pass bf16) + online-softmax partials ----------------
__global__ void __launch_bounds__(256) logits_nll_kernel(
    const __nv_bfloat16* __restrict__ Ahi,
    const __nv_bfloat16* __restrict__ Bhi,
    const float* __restrict__ bias, const int* __restrict__ ys)
{
    extern __shared__ char smem[];
    const uint32_t sbase = smem_u32(smem);
    const int tid = threadIdx.x, lid = tid & 31, wid = tid >> 5;
    const int wm = (wid & 1) * 64, wn = (wid >> 1) * 32;
    const int bn = blockIdx.x * 128, bm = blockIdx.y * 128;
    float acc[4][4][4];
    gemm_main1(smem, sbase, Ahi, Bhi, bm, bn, H_, acc);

    float* smc = (float*)smem;
    const int mrow = (lid >> 2), ncol = (lid & 3) * 2;
    #pragma unroll
    for (int mt = 0; mt < 4; mt++) {
        #pragma unroll
        for (int nt = 0; nt < 4; nt++) {
            int r = wm + mt * 16 + mrow;
            int c = wn + nt * 8 + ncol;
            float b0 = bias[bn + c], b1 = bias[bn + c + 1];
            smc[r * 132 + c]             = acc[mt][nt][0] + b0;
            smc[r * 132 + c + 1]         = acc[mt][nt][1] + b1;
            smc[(r + 8) * 132 + c]       = acc[mt][nt][2] + b0;
            smc[(r + 8) * 132 + c + 1]   = acc[mt][nt][3] + b1;
        }
    }
    __syncthreads();

    int row = tid >> 1, half = tid & 1;
    const float* lr = smc + row * 132 + half * 64;
    float m = -3.4e38f, s = 0.f;
    #pragma unroll 8
    for (int c = 0; c < 64; c++) {
        float x = lr[c];
        float nm = fmaxf(m, x);
        s = s * __expf(m - nm) + __expf(x - nm);
        m = nm;
    }
    float m2 = __shfl_xor_sync(0xFFFFFFFF, m, 1);
    float s2 = __shfl_xor_sync(0xFFFFFFFF, s, 1);
    float M = fmaxf(m, m2);
    float S = s * __expf(m - M) + s2 * __expf(m2 - M);
    int grow = bm + row;
    if (half == 0) {
        d_pmax[(size_t)grow * NCB + blockIdx.x] = M;
        d_psum[(size_t)grow * NCB + blockIdx.x] = S;
        int target = ys[grow];
        if (target >= bn && target < bn + 128)
            d_tlogit[grow] = smc[row * 132 + (target - bn)];
    }
}

__global__ void nll_reduce_kernel(float* __restrict__ rownll) {
    int row = blockIdx.x * 256 + threadIdx.x;
    const float* pm = d_pmax + (size_t)row * NCB;
    const float* ps = d_psum + (size_t)row * NCB;
    float m = -3.4e38f, s = 0.f;
    #pragma unroll 8
    for (int c = 0; c < NCB; c++) {
        float m2 = pm[c], s2 = ps[c];
        float M = fmaxf(m, m2);
        s = s * __expf(m - M) + s2 * __expf(m2 - M);
        m = M;
    }
    rownll[row] = -(d_tlogit[row] - m - logf(s));
}

__global__ void mean_kernel(const float* __restrict__ rownll, float* __restrict__ out) {
    __shared__ float sred[256];
    int tid = threadIdx.x;
    float s = 0.f;
    for (int i = tid; i < B_*T_; i += 256) s += rownll[i];
    sred[tid] = s; __syncthreads();
    for (int k = 128; k > 0; k >>= 1) {
        if (tid < k) sred[tid] += sred[tid + k];
        __syncthreads();
    }
    if (tid == 0) out[0] = sred[0] / (float)(B_*T_);
}

// ---------------- persistent recurrence: fine-grained producer-group sync ----------------
__global__ void reset_bar_kernel() {
    int i = threadIdx.x;
    if (i < 128) g_hcnt[i] = 0u;
    else if (i < 256) g_mcnt[i - 128] = 0u;
}

#define S_WBHI  0
#define S_WBLO  65536
#define S_WAHI  131072
#define S_WALO  147456
#define S_STG   163840
#define RS_BYTES 229376

__global__ void __launch_bounds__(256) recur_kernel(
    const float* __restrict__ zx, const float* __restrict__ mxp,
    const float* __restrict__ wmhnT, const float* __restrict__ whnT,
    __nv_bfloat16* __restrict__ hshi, __nv_bfloat16* __restrict__ hslo)
{
    extern __shared__ char smc[];
    float* stg = (float*)(smc + S_STG);
    const uint32_t sbase = smem_u32(smc);
    const int bk = blockIdx.x, tid = threadIdx.x;

    // one-time weight preload (bf16 hi/lo, ldmatrix-swizzled rows)
    #pragma unroll 4
    for (int p = 0; p < 32; p++) {
        int col = (p >> 3) * H_ + bk * 8 + (p & 7);
        float4 v = ((const float4*)(whnT + (size_t)col * H_))[tid];
        __nv_bfloat16 hx = __float2bfloat16(v.x), hy = __float2bfloat16(v.y);
        __nv_bfloat16 hz = __float2bfloat16(v.z), hw = __float2bfloat16(v.w);
        __nv_bfloat16 lx = __float2bfloat16(v.x - __bfloat162float(hx));
        __nv_bfloat16 ly = __float2bfloat16(v.y - __bfloat162float(hy));
        __nv_bfloat16 lz = __float2bfloat16(v.z - __bfloat162float(hz));
        __nv_bfloat16 lw = __float2bfloat16(v.w - __bfloat162float(hw));
        uint32_t off = p * 2048 + ((tid * 8) ^ ((p & 7) * 16));
        *(uint2*)(smc + S_WBHI + off) = make_uint2(pk(hx, hy), pk(hz, hw));
        *(uint2*)(smc + S_WBLO + off) = make_uint2(pk(lx, ly), pk(lz, lw));
    }
    #pragma unroll
    for (int p = 0; p < 8; p++) {
        int col = bk * 8 + p;
        float4 v = ((const float4*)(wmhnT + (size_t)col * H_))[tid];
        __nv_bfloat16 hx = __float2bfloat16(v.x), hy = __float2bfloat16(v.y);
        __nv_bfloat16 hz = __float2bfloat16(v.z), hw = __float2bfloat16(v.w);
        __nv_bfloat16 lx = __float2bfloat16(v.x - __bfloat162float(hx));
        __nv_bfloat16 ly = __float2bfloat16(v.y - __bfloat162float(hy));
        __nv_bfloat16 lz = __float2bfloat16(v.z - __bfloat162float(hz));
        __nv_bfloat16 lw = __float2bfloat16(v.w - __bfloat162float(hw));
        uint32_t off = p * 2048 + ((tid * 8) ^ (p * 16));
        *(uint2*)(smc + S_WAHI + off) = make_uint2(pk(hx, hy), pk(hz, hw));
        *(uint2*)(smc + S_WALO + off) = make_uint2(pk(lx, ly), pk(lz, lw));
    }
    // init h(0)=0 for this block's 8 columns, then announce
    if (tid < 128) {
        int b = tid >> 3, col = bk*8 + (tid & 7);
        ((short*)d_hhi)[b*H_ + col] = 0;
        ((short*)d_hlo)[b*H_ + col] = 0;
    }
    __syncthreads();
    if (tid == 0)
        asm volatile("red.release.gpu.global.add.u32 [%0], %1;"
                     :: "l"(g_hcnt + (bk >> 4) * 8), "r"(1u) : "memory");

    const int l = tid & 31, wql = tid >> 5;
    const int arow = (l & 7) + ((l >> 3) & 1) * 8;
    const uint32_t ax = (uint32_t)((arow & 7) * 16);
    const uint32_t asel = ((uint32_t)(l >> 4)) << 4;
    const int brow7 = l & 7;
    const uint32_t bx = (uint32_t)(brow7 * 16);
    const uint32_t bsel = ((uint32_t)((l >> 3) & 1)) << 4;
    int rci[2], rb[2]; size_t rzoff[2];
    #pragma unroll
    for (int o = 0; o < 2; o++) {
        int out = tid + o*256;
        rci[o] = out >> 4; rb[o] = out & 15;
        int q = rci[o] >> 3, j0 = rci[o] & 7;
        rzoff[o] = (size_t)rb[o]*T_*FH + (size_t)q*H_ + bk*8 + j0;
    }
    const int bG = tid >> 3, j0G = tid & 7;
    float creg = 0.f;
    const unsigned* hcnt = g_hcnt + wql * 8;
    const unsigned* mcnt = g_mcnt + wql * 8;

    for (int t = 0; t < T_; t++) {
        float zpre0 = __ldg(&zx[rzoff[0] + (size_t)t*FH]);
        float zpre1 = __ldg(&zx[rzoff[1] + (size_t)t*FH]);
        float mxv = 0.f;
        if (tid < 128) mxv = __ldg(&mxp[(size_t)(bG*T_ + t)*H_ + bk*8 + j0G]);
        const unsigned gen = 16u * (unsigned)(t + 1);

        // ---- phase A: wait own producer group, stage own h k-slice, mma ----
        wait_cnt(hcnt, gen);
        #pragma unroll
        for (int p = 0; p < 16; p++) {
            int i = (p & 7) * 32 + l;            // 0..255 chunks per half
            int half = p >> 3;
            int b = i >> 4, cc = i & 15;
            const uint4* src = (const uint4*)(half ? d_hlo : d_hhi);
            uint4 v = __ldcg(src + b*128 + wql*16 + cc);
            *(uint4*)(smc + S_STG + half*32768 + b*2048
                      + ((wql*256 + cc*16) ^ ((b&7)*16))) = v;
        }
        __syncwarp();

        float accA[4] = {0.f, 0.f, 0.f, 0.f};
        #pragma unroll
        for (int kc = 0; kc < 8; kc++) {
            uint32_t kb = (uint32_t)(wql*256 + kc*32);
            uint32_t aaddr = sbase + S_STG + (uint32_t)arow*2048 + ((kb + asel) ^ ax);
            uint32_t ah[4], al[4];
            ldm_x4(ah, aaddr);
            ldm_x4(al, aaddr + 32768);
            uint32_t bkb = (kb + bsel) ^ bx;
            uint32_t baddr = sbase + S_WAHI + (uint32_t)brow7*2048 + bkb;
            uint32_t bh2[2], bl2[2];
            ldm_x2(bh2, baddr);
            ldm_x2(bl2, baddr + 16384);
            mma_bf16(accA, ah, bh2);
            mma_bf16(accA, ah, bl2);
            mma_bf16(accA, al, bh2);
        }
        __syncthreads();     // all warps done with h stage; overlay as part[]
        {
            int bq = l >> 2, cq = (l & 3) * 2;
            stg[(cq*16 + bq)*9 + wql]           = accA[0];
            stg[((cq+1)*16 + bq)*9 + wql]       = accA[1];
            stg[(cq*16 + bq + 8)*9 + wql]       = accA[2];
            stg[((cq+1)*16 + bq + 8)*9 + wql]   = accA[3];
        }
        __syncthreads();
        if (tid < 128) {
            const float* pp = stg + (j0G*16 + bG)*9;
            float s = ((pp[0]+pp[1]) + (pp[2]+pp[3])) + ((pp[4]+pp[5]) + (pp[6]+pp[7]));
            float mval = s * mxv;
            __nv_bfloat16 mh = __float2bfloat16(mval);
            __nv_bfloat16 ml = __float2bfloat16(mval - __bfloat162float(mh));
            __stcg((short*)&d_mthi[bG*H_ + bk*8 + j0G], *(short*)&mh);
            __stcg((short*)&d_mtlo[bG*H_ + bk*8 + j0G], *(short*)&ml);
        }
        __syncthreads();
        if (tid == 0)
            asm volatile("red.release.gpu.global.add.u32 [%0], %1;"
                         :: "l"(g_mcnt + (bk >> 4) * 8), "r"(1u) : "memory");

        // ---- phase B: wait own producer group, stage own m k-slice, mma ----
        wait_cnt(mcnt, gen);
        #pragma unroll
        for (int p = 0; p < 16; p++) {
            int i = (p & 7) * 32 + l;
            int half = p >> 3;
            int b = i >> 4, cc = i & 15;
            const uint4* src = (const uint4*)(half ? d_mtlo : d_mthi);
            uint4 v = __ldcg(src + b*128 + wql*16 + cc);
            *(uint4*)(smc + S_STG + half*32768 + b*2048
                      + ((wql*256 + cc*16) ^ ((b&7)*16))) = v;
        }
        __syncwarp();

        float acc[4][4];
        #pragma unroll
        for (int nt = 0; nt < 4; nt++)
            #pragma unroll
            for (int u = 0; u < 4; u++) acc[nt][u] = 0.f;
        #pragma unroll
        for (int kc = 0; kc < 8; kc++) {
            uint32_t kb = (uint32_t)(wql*256 + kc*32);
            uint32_t aaddr = sbase + S_STG + (uint32_t)arow*2048 + ((kb + asel) ^ ax);
            uint32_t ah[4], al[4];
            ldm_x4(ah, aaddr);
            ldm_x4(al, aaddr + 32768);
            uint32_t bkb = (kb + bsel) ^ bx;
            #pragma unroll
            for (int nt = 0; nt < 4; nt++) {
                uint32_t baddr = sbase + S_WBHI + (uint32_t)(nt*8 + brow7)*2048 + bkb;
                uint32_t bh[2], bl[2];
                ldm_x2(bh, baddr);
                ldm_x2(bl, baddr + 65536);
                mma_bf16(acc[nt], ah, bh);
                mma_bf16(acc[nt], ah, bl);
                mma_bf16(acc[nt], al, bh);
            }
        }
        __syncthreads();     // all warps done with m stage; overlay as part[]
        {
            int bq = l >> 2, cq = (l & 3) * 2;
            #pragma unroll
            for (int nt = 0; nt < 4; nt++) {
                int c0 = nt*8 + cq;
                stg[(c0*16 + bq)*9 + wql]          = acc[nt][0];
                stg[((c0+1)*16 + bq)*9 + wql]      = acc[nt][1];
                stg[(c0*16 + bq + 8)*9 + wql]      = acc[nt][2];
                stg[((c0+1)*16 + bq + 8)*9 + wql]  = acc[nt][3];
            }
        }
        __syncthreads();

        {
            const float* p0 = stg + (rci[0]*16 + rb[0])*9;
            float s0 = ((p0[0]+p0[1]) + (p0[2]+p0[3])) + ((p0[4]+p0[5]) + (p0[6]+p0[7]));
            stg[8192 + rb[0]*32 + rci[0]] = zpre0 + s0;
            const float* p1 = stg + (rci[1]*16 + rb[1])*9;
            float s1 = ((p1[0]+p1[1]) + (p1[2]+p1[3])) + ((p1[4]+p1[5]) + (p1[6]+p1[7]));
            stg[8192 + rb[1]*32 + rci[1]] = zpre1 + s1;
        }
        __syncthreads();

        if (tid < 128) {
            float zi = stg[8192 + bG*32 +      j0G];
            float zf = stg[8192 + bG*32 +  8 + j0G];
            float zo = stg[8192 + bG*32 + 16 + j0G];
            float zu = stg[8192 + bG*32 + 24 + j0G];
            float ig = 1.f / (1.f + expf(-zi));
            float fg = 1.f / (1.f + expf(-zf));
            float og = 1.f / (1.f + expf(-zo));
            float ug = tanhf(zu);
            creg = fg * creg + ig * ug;
            float h = og * tanhf(creg);
            int col = bk*8 + j0G;
            __nv_bfloat16 hh = __float2bfloat16(h);
            __nv_bfloat16 hl = __float2bfloat16(h - __bfloat162float(hh));
            __stcg((short*)&d_hhi[bG*H_ + col], *(short*)&hh);
            __stcg((short*)&d_hlo[bG*H_ + col], *(short*)&hl);
            size_t hidx = (size_t)(bG*T_ + t)*H_ + col;
            hshi[hidx] = hh;
            hslo[hidx] = hl;
        }
        __syncthreads();
        if (tid == 0)
            asm volatile("red.release.gpu.global.add.u32 [%0], %1;"
                         :: "l"(g_hcnt + (bk >> 4) * 8), "r"(1u) : "memory");
    }
}

// ---------------- launcher ----------------
extern "C" void kernel_launch(void* const* d_in, const int* in_sizes, int n_in,
                              void* d_out, int out_size) {
    (void)in_sizes; (void)n_in; (void)out_size;
    const int*   xs      = (const int*)  d_in[0];
    const int*   ys      = (const int*)  d_in[1];
    const float* embed_w = (const float*)d_in[2];
    const float* wx      = (const float*)d_in[3];
    const float* wh      = (const float*)d_in[4];
    const float* wmx     = (const float*)d_in[5];
    const float* wmh     = (const float*)d_in[6];
    const float* bb      = (const float*)d_in[7];
    const float* gx      = (const float*)d_in[8];
    const float* gh      = (const float*)d_in[9];
    const float* gmx     = (const float*)d_in[10];
    const float* gmh     = (const float*)d_in[11];
    const float* pred_w  = (const float*)d_in[12];
    const float* pred_b  = (const float*)d_in[13];
    float* out = (float*)d_out;

    float *p_whnT, *p_wmhnT, *p_zx, *p_mx, *p_rownll;
    float *p_nwx, *p_nwh, *p_nwmx, *p_nwmh;
    __nv_bfloat16 *p_xhi, *p_xlo, *p_wxnThi, *p_wxnTlo, *p_wmxnThi, *p_wmxnTlo;
    __nv_bfloat16 *p_pwhi, *p_pwlo, *p_hshi, *p_hslo;
    cudaGetSymbolAddress((void**)&p_whnT,    d_whnT);
    cudaGetSymbolAddress((void**)&p_wmhnT,   d_wmhnT);
    cudaGetSymbolAddress((void**)&p_zx,      d_zx);
    cudaGetSymbolAddress((void**)&p_mx,      d_mx);
    cudaGetSymbolAddress((void**)&p_rownll,  d_rownll);
    cudaGetSymbolAddress((void**)&p_nwx,     d_nwx);
    cudaGetSymbolAddress((void**)&p_nwh,     d_nwh);
    cudaGetSymbolAddress((void**)&p_nwmx,    d_nwmx);
    cudaGetSymbolAddress((void**)&p_nwmh,    d_nwmh);
    cudaGetSymbolAddress((void**)&p_xhi,     d_xhi);
    cudaGetSymbolAddress((void**)&p_xlo,     d_xlo);
    cudaGetSymbolAddress((void**)&p_wxnThi,  d_wxnThi);
    cudaGetSymbolAddress((void**)&p_wxnTlo,  d_wxnTlo);
    cudaGetSymbolAddress((void**)&p_wmxnThi, d_wmxnThi);
    cudaGetSymbolAddress((void**)&p_wmxnTlo, d_wmxnTlo);
    cudaGetSymbolAddress((void**)&p_pwhi,    d_pwhi);
    cudaGetSymbolAddress((void**)&p_pwlo,    d_pwlo);
    cudaGetSymbolAddress((void**)&p_hshi,    d_hshi);
    cudaGetSymbolAddress((void**)&p_hslo,    d_hslo);

    static bool attr_set = false;
    if (!attr_set) {
        cudaFuncSetAttribute(recur_kernel, cudaFuncAttributeMaxDynamicSharedMemorySize, RS_BYTES);
        cudaFuncSetAttribute(mma_gemm<true>,  cudaFuncAttributeMaxDynamicSharedMemorySize, GSMEM);
        cudaFuncSetAttribute(mma_gemm<false>, cudaFuncAttributeMaxDynamicSharedMemorySize, GSMEM);
        cudaFuncSetAttribute(logits_nll_kernel, cudaFuncAttributeMaxDynamicSharedMemorySize, GSMEM);
        attr_set = true;
    }

    // weight norm
    zero_norms_kernel<<<16, 256>>>();
    sumsq_kernel<<<dim3(FH/256, E_/32), 256>>>(wx,  p_nwx,  E_, FH);
    sumsq_kernel<<<dim3(FH/256, H_/32), 256>>>(wh,  p_nwh,  H_, FH);
    sumsq_kernel<<<dim3(H_/256, E_/32), 256>>>(wmx, p_nwmx, E_, H_);
    sumsq_kernel<<<dim3(H_/256, H_/32), 256>>>(wmh, p_nwmh, H_, H_);
    scaleT_bf16_kernel<<<dim3(FH/32, E_/32), dim3(32,8)>>>(wx,  gx,  p_nwx,  p_wxnThi,  p_wxnTlo,  E_, FH);
    scaleT_bf16_kernel<<<dim3(H_/32, E_/32), dim3(32,8)>>>(wmx, gmx, p_nwmx, p_wmxnThi, p_wmxnTlo, E_, H_);
    scaleT_kernel<<<dim3(FH/32, H_/32), dim3(32,8)>>>(wh,  gh,  p_nwh,  p_whnT,  H_, FH);
    scaleT_kernel<<<dim3(H_/32, H_/32), dim3(32,8)>>>(wmh, gmh, p_nwmh, p_wmhnT, H_, H_);
    split_kernel<<<(int)(((size_t)V_*H_ + 255)/256), 256>>>(pred_w, p_pwhi, p_pwlo, (size_t)V_*H_);

    // embedding
    embed_kernel<<<B_*T_, 128>>>(xs, embed_w, p_xhi, p_xlo);

    // input projections (3-pass — precision-critical, feeds recurrence)
    mma_gemm<true ><<<dim3(FH/128, (B_*T_)/128), 256, GSMEM>>>(
        p_xhi, p_xlo, p_wxnThi, p_wxnTlo, bb, p_zx, B_*T_, FH, E_);
    mma_gemm<false><<<dim3(H_/128, (B_*T_)/128), 256, GSMEM>>>(
        p_xhi, p_xlo, p_wmxnThi, p_wmxnTlo, (const float*)nullptr, p_mx, B_*T_, H_, E_);

    // recurrence (fine-grained producer-group sync)
    reset_bar_kernel<<<1, 256>>>();
    recur_kernel<<<NBLK, 256, RS_BYTES>>>(
        p_zx, p_mx, p_wmhnT, p_whnT, p_hshi, p_hslo);

    // fused logits (1-pass bf16) + softmax partials + loss
    logits_nll_kernel<<<dim3(NCB, (B_*T_)/128), 256, GSMEM>>>(
        p_hshi, p_pwhi, pred_b, ys);
    nll_reduce_kernel<<<(B_*T_)/256, 256>>>(p_rownll);
    mean_kernel<<<1, 256>>>(p_rownll, out);
}

// round 14
// speedup vs baseline: 1.2697x; 1.2697x over previous
#include <cuda_runtime.h>
#include <cuda_bf16.h>
#include <cstdint>

#define B_  16
#define T_  512
#define V_  8192
#define E_  512
#define H_  1024
#define FH  4096
#define NBLK 128
#define NCB (V_/128)        // 64 column-blocks for logits

// ---------------- device scratch ----------------
__device__ __nv_bfloat16 d_xhi[B_*T_*E_], d_xlo[B_*T_*E_];
__device__ __nv_bfloat16 d_wxnThi[(size_t)FH*E_], d_wxnTlo[(size_t)FH*E_];
__device__ __nv_bfloat16 d_wmxnThi[H_*E_], d_wmxnTlo[H_*E_];
__device__ __nv_bfloat16 d_pwhi[(size_t)V_*H_];
__device__ __nv_bfloat16 d_hshi[B_*T_*H_];
__device__ float d_whnT[(size_t)FH*H_];
__device__ float d_wmhnT[H_*H_];
__device__ float d_nwx[FH], d_nwh[FH], d_nwmx[H_], d_nwmh[H_];
__device__ float d_zx[(size_t)B_*T_*FH];
__device__ float d_mx[B_*T_*H_];
__device__ __nv_bfloat16 d_hhi[B_*H_], d_hlo[B_*H_];
__device__ __nv_bfloat16 d_mthi[B_*H_], d_mtlo[B_*H_];
__device__ float d_pmax[(size_t)B_*T_*NCB];
__device__ float d_psum[(size_t)B_*T_*NCB];
__device__ float d_tlogit[B_*T_];
__device__ float d_rownll[B_*T_];
__device__ unsigned g_barcnt;

// ---------------- helpers ----------------
__device__ __forceinline__ uint32_t smem_u32(const void* p) {
    uint32_t a;
    asm("{ .reg .u64 t; cvta.to.shared.u64 t, %1; cvt.u32.u64 %0, t; }" : "=r"(a) : "l"(p));
    return a;
}
__device__ __forceinline__ void ldm_x4(uint32_t* r, uint32_t addr) {
    asm volatile("ldmatrix.sync.aligned.m8n8.x4.shared.b16 {%0,%1,%2,%3}, [%4];"
                 : "=r"(r[0]), "=r"(r[1]), "=r"(r[2]), "=r"(r[3]) : "r"(addr));
}
__device__ __forceinline__ void ldm_x2(uint32_t* r, uint32_t addr) {
    asm volatile("ldmatrix.sync.aligned.m8n8.x2.shared.b16 {%0,%1}, [%2];"
                 : "=r"(r[0]), "=r"(r[1]) : "r"(addr));
}
__device__ __forceinline__ void mma_bf16(float* c, const uint32_t* a, const uint32_t* b) {
    asm volatile("mma.sync.aligned.m16n8k16.row.col.f32.bf16.bf16.f32 "
                 "{%0,%1,%2,%3}, {%4,%5,%6,%7}, {%8,%9}, {%0,%1,%2,%3};"
                 : "+f"(c[0]), "+f"(c[1]), "+f"(c[2]), "+f"(c[3])
                 : "r"(a[0]), "r"(a[1]), "r"(a[2]), "r"(a[3]), "r"(b[0]), "r"(b[1]));
}
__device__ __forceinline__ uint32_t pk(__nv_bfloat16 a, __nv_bfloat16 b) {
    __nv_bfloat162 t = __halves2bfloat162(a, b);
    return *(uint32_t*)&t;
}
__device__ __forceinline__ void cpa16(uint32_t saddr, const void* g) {
    asm volatile("cp.async.cg.shared.global [%0], [%1], 16;" :: "r"(saddr), "l"(g) : "memory");
}

// ---------------- weight norm ----------------
__global__ void zero_norms_kernel() {
    int i = blockIdx.x * 256 + threadIdx.x;
    if (i < FH) { d_nwx[i] = 0.f; d_nwh[i] = 0.f; }
    if (i < H_) { d_nwmx[i] = 0.f; d_nwmh[i] = 0.f; }
}
// fused sumsq over the 4 weight matrices: blockIdx.y selects matrix
__global__ void sumsq4_kernel(const float* __restrict__ wx, const float* __restrict__ wh,
                              const float* __restrict__ wmx, const float* __restrict__ wmh) {
    int id = blockIdx.y;
    const float* w; float* nrm; int K, N;
    if (id == 0)      { w = wx;  nrm = d_nwx;  K = E_; N = FH; }
    else if (id == 1) { w = wh;  nrm = d_nwh;  K = H_; N = FH; }
    else if (id == 2) { w = wmx; nrm = d_nwmx; K = E_; N = H_; }
    else              { w = wmh; nrm = d_nwmh; K = H_; N = H_; }
    int j = blockIdx.x * 256 + threadIdx.x;
    int k0 = blockIdx.z * 32;
    if (j >= N || k0 >= K) return;
    float ss = 0.f;
    #pragma unroll 4
    for (int k = k0; k < k0 + 32; k++) { float v = w[(size_t)k*N + j]; ss += v*v; }
    atomicAdd(&nrm[j], ss);
}
__global__ void scaleT_kernel(const float* __restrict__ w, const float* __restrict__ g,
                              const float* __restrict__ nrm, float* __restrict__ out,
                              int K, int N) {
    __shared__ float tile[32][33];
    int n0 = blockIdx.x * 32, k0 = blockIdx.y * 32;
    int tx = threadIdx.x, ty = threadIdx.y;
    for (int r = ty; r < 32; r += 8)
        tile[r][tx] = w[(size_t)(k0 + r)*N + n0 + tx];
    __syncthreads();
    for (int r = ty; r < 32; r += 8) {
        int n = n0 + r;
        float s = g[n] / fmaxf(sqrtf(nrm[n]), 1e-12f);
        out[(size_t)n*K + k0 + tx] = tile[tx][r] * s;
    }
}
__global__ void scaleT_bf16_kernel(const float* __restrict__ w, const float* __restrict__ g,
                                   const float* __restrict__ nrm,
                                   __nv_bfloat16* __restrict__ ohi,
                                   __nv_bfloat16* __restrict__ olo,
                                   int K, int N) {
    __shared__ float tile[32][33];
    int n0 = blockIdx.x * 32, k0 = blockIdx.y * 32;
    int tx = threadIdx.x, ty = threadIdx.y;
    for (int r = ty; r < 32; r += 8)
        tile[r][tx] = w[(size_t)(k0 + r)*N + n0 + tx];
    __syncthreads();
    for (int r = ty; r < 32; r += 8) {
        int n = n0 + r;
        float s = g[n] / fmaxf(sqrtf(nrm[n]), 1e-12f);
        float v = tile[tx][r] * s;
        __nv_bfloat16 hi = __float2bfloat16(v);
        ohi[(size_t)n*K + k0 + tx] = hi;
        olo[(size_t)n*K + k0 + tx] = __float2bfloat16(v - __bfloat162float(hi));
    }
}
// hi-only split (logits path is 1-pass)
__global__ void split_hi_kernel(const float* __restrict__ w,
                                __nv_bfloat16* __restrict__ ohi, size_t total) {
    size_t i = (size_t)blockIdx.x * 256 + threadIdx.x;
    if (i >= total) return;
    ohi[i] = __float2bfloat16(w[i]);
}

// ---------------- embedding ----------------
__global__ void embed_kernel(const int* __restrict__ xs, const float* __restrict__ ew,
                             __nv_bfloat16* __restrict__ xhi, __nv_bfloat16* __restrict__ xlo) {
    int r = blockIdx.x;
    int idx = xs[r];
    const float4* src = (const float4*)(ew + (size_t)idx * E_);
    float4 v = src[threadIdx.x];
    if (idx == 0) v = make_float4(0.f, 0.f, 0.f, 0.f);
    size_t base = (size_t)r * E_ + threadIdx.x * 4;
    float vv[4] = {v.x, v.y, v.z, v.w};
    #pragma unroll
    for (int u = 0; u < 4; u++) {
        __nv_bfloat16 hi = __float2bfloat16(vv[u]);
        xhi[base + u] = hi;
        xlo[base + u] = __float2bfloat16(vv[u] - __bfloat162float(hi));
    }
}

// ---------------- mma.sync split-bf16 GEMM cores ----------------
#define GSMEM 131072

template<bool THIRD>
__device__ __forceinline__ void gemm_main3(
    char* smem, uint32_t sbase,
    const __nv_bfloat16* Ahi, const __nv_bfloat16* Alo,
    const __nv_bfloat16* Bhi, const __nv_bfloat16* Blo,
    int bm, int bn, int K, float acc[4][4][4])
{
    const int tid = threadIdx.x, lid = tid & 31, wid = tid >> 5;
    const int wm = (wid & 1) * 64, wn = (wid >> 1) * 32;
    #pragma unroll
    for (int mt = 0; mt < 4; mt++)
        #pragma unroll
        for (int nt = 0; nt < 4; nt++)
            #pragma unroll
            for (int u = 0; u < 4; u++) acc[mt][nt][u] = 0.f;

    auto issue = [&](int ch, int buf) {
        int k0 = ch << 6;
        #pragma unroll
        for (int p = 0; p < 16; p++) {
            int i = tid + p * 256;
            int tile = i >> 10, j = i & 1023;
            int row = j >> 3, c = j & 7;
            const __nv_bfloat16* src = (tile == 0) ? Ahi : (tile == 1) ? Alo
                                     : (tile == 2) ? Bhi : Blo;
            int grow = ((tile < 2) ? bm : bn) + row;
            uint32_t sa = sbase + (uint32_t)buf*65536 + tile*16384
                        + (row * 8 + (c ^ (row & 7))) * 16;
            cpa16(sa, src + (size_t)grow * K + k0 + c * 8);
        }
        asm volatile("cp.async.commit_group;" ::: "memory");
    };

    const int nchunk = K >> 6;
    issue(0, 0);
    for (int ch = 0; ch < nchunk; ch++) {
        if (ch + 1 < nchunk) {
            issue(ch + 1, (ch + 1) & 1);
            asm volatile("cp.async.wait_group 1;" ::: "memory");
        } else {
            asm volatile("cp.async.wait_group 0;" ::: "memory");
        }
        __syncthreads();
        const uint32_t boff = sbase + (uint32_t)((ch & 1) * 65536);
        #pragma unroll
        for (int ks = 0; ks < 4; ks++) {
            uint32_t bh[4][2], bl[4][2];
            {
                int row = wn + (lid & 7);
                int cc = 2 * ks + ((lid >> 3) & 1);
                #pragma unroll
                for (int nt = 0; nt < 4; nt++) {
                    int r = row + nt * 8;
                    uint32_t addr = boff + 32768 + (r * 8 + (cc ^ (r & 7))) * 16;
                    ldm_x2(bh[nt], addr);
                    ldm_x2(bl[nt], addr + 16384);
                }
            }
            #pragma unroll
            for (int mt = 0; mt < 4; mt++) {
                int r = wm + mt * 16 + (lid & 7) + ((lid >> 3) & 1) * 8;
                int cc = 2 * ks + (lid >> 4);
                uint32_t addr = boff + (r * 8 + (cc ^ (r & 7))) * 16;
                uint32_t ah[4], al[4];
                ldm_x4(ah, addr);
                ldm_x4(al, addr + 16384);
                #pragma unroll
                for (int nt = 0; nt < 4; nt++) {
                    mma_bf16(acc[mt][nt], ah, bh[nt]);
                    mma_bf16(acc[mt][nt], ah, bl[nt]);
                    if (THIRD) mma_bf16(acc[mt][nt], al, bh[nt]);
                }
            }
        }
        __syncthreads();
    }
}

__device__ __forceinline__ void gemm_main1(
    char* smem, uint32_t sbase,
    const __nv_bfloat16* Ahi, const __nv_bfloat16* Bhi,
    int bm, int bn, int K, float acc[4][4][4])
{
    const int tid = threadIdx.x, lid = tid & 31, wid = tid >> 5;
    const int wm = (wid & 1) * 64, wn = (wid >> 1) * 32;
    #pragma unroll
    for (int mt = 0; mt < 4; mt++)
        #pragma unroll
        for (int nt = 0; nt < 4; nt++)
            #pragma unroll
            for (int u = 0; u < 4; u++) acc[mt][nt][u] = 0.f;

    auto issue = [&](int ch, int buf) {
        int k0 = ch << 6;
        #pragma unroll
        for (int p = 0; p < 8; p++) {
            int i = tid + p * 256;
            int tile = i >> 10, j = i & 1023;
            int row = j >> 3, c = j & 7;
            const __nv_bfloat16* src = (tile == 0) ? Ahi : Bhi;
            int grow = ((tile == 0) ? bm : bn) + row;
            uint32_t sa = sbase + (uint32_t)buf*32768 + tile*16384
                        + (row * 8 + (c ^ (row & 7))) * 16;
            cpa16(sa, src + (size_t)grow * K + k0 + c * 8);
        }
        asm volatile("cp.async.commit_group;" ::: "memory");
    };

    const int nchunk = K >> 6;
    issue(0, 0);
    for (int ch = 0; ch < nchunk; ch++) {
        if (ch + 1 < nchunk) {
            issue(ch + 1, (ch + 1) & 1);
            asm volatile("cp.async.wait_group 1;" ::: "memory");
        } else {
            asm volatile("cp.async.wait_group 0;" ::: "memory");
        }
        __syncthreads();
        const uint32_t boff = sbase + (uint32_t)((ch & 1) * 32768);
        #pragma unroll
        for (int ks = 0; ks < 4; ks++) {
            uint32_t bh[4][2];
            {
                int row = wn + (lid & 7);
                int cc = 2 * ks + ((lid >> 3) & 1);
                #pragma unroll
                for (int nt = 0; nt < 4; nt++) {
                    int r = row + nt * 8;
                    ldm_x2(bh[nt], boff + 16384 + (r * 8 + (cc ^ (r & 7))) * 16);
                }
            }
            #pragma unroll
            for (int mt = 0; mt < 4; mt++) {
                int r = wm + mt * 16 + (lid & 7) + ((lid >> 3) & 1) * 8;
                int cc = 2 * ks + (lid >> 4);
                uint32_t ah[4];
                ldm_x4(ah, boff + (r * 8 + (cc ^ (r & 7))) * 16);
                #pragma unroll
                for (int nt = 0; nt < 4; nt++)
                    mma_bf16(acc[mt][nt], ah, bh[nt]);
            }
        }
        __syncthreads();
    }
}

template<bool BIAS, bool THIRD>
__global__ void __launch_bounds__(256) mma_gemm(
    const __nv_bfloat16* __restrict__ Ahi, const __nv_bfloat16* __restrict__ Alo,
    const __nv_bfloat16* __restrict__ Bhi, const __nv_bfloat16* __restrict__ Blo,
    const float* __restrict__ bias, float* __restrict__ C,
    int M, int N, int K)
{
    extern __shared__ char smem[];
    const uint32_t sbase = smem_u32(smem);
    const int tid = threadIdx.x, lid = tid & 31, wid = tid >> 5;
    const int wm = (wid & 1) * 64, wn = (wid >> 1) * 32;
    const int bn = blockIdx.x * 128, bm = blockIdx.y * 128;
    float acc[4][4][4];
    gemm_main3<THIRD>(smem, sbase, Ahi, Alo, Bhi, Blo, bm, bn, K, acc);

    const int mrow = (lid >> 2), ncol = (lid & 3) * 2;
    #pragma unroll
    for (int mt = 0; mt < 4; mt++) {
        #pragma unroll
        for (int nt = 0; nt < 4; nt++) {
            int row0 = bm + wm + mt * 16 + mrow;
            int col = bn + wn + nt * 8 + ncol;
            float2 v0 = make_float2(acc[mt][nt][0], acc[mt][nt][1]);
            float2 v1 = make_float2(acc[mt][nt][2], acc[mt][nt][3]);
            if (BIAS) {
                float b0 = bias[col], b1 = bias[col + 1];
                v0.x += b0; v0.y += b1;
                v1.x += b0; v1.y += b1;
            }
            *(float2*)&C[(size_t)row0 * N + col] = v0;
            *(float2*)&C[(size_t)(row0 + 8) * N + col] = v1;
        }
    }
}

// ---------------- fused logits (1-pass bf16) + online-softmax partials ----------------
__global__ void __launch_bounds__(256) logits_nll_kernel(
    const __nv_bfloat16* __restrict__ Ahi,
    const __nv_bfloat16* __restrict__ Bhi,
    const float* __restrict__ bias, const int* __restrict__ ys)
{
    extern __shared__ char smem[];
    const uint32_t sbase = smem_u32(smem);
    const int tid = threadIdx.x, lid = tid & 31, wid = tid >> 5;
    const int wm = (wid & 1) * 64, wn = (wid >> 1) * 32;
    const int bn = blockIdx.x * 128, bm = blockIdx.y * 128;
    float acc[4][4][4];
    gemm_main1(smem, sbase, Ahi, Bhi, bm, bn, H_, acc);

    float* smc = (float*)smem;
    const int mrow = (lid >> 2), ncol = (lid & 3) * 2;
    #pragma unroll
    for (int mt = 0; mt < 4; mt++) {
        #pragma unroll
        for (int nt = 0; nt < 4; nt++) {
            int r = wm + mt * 16 + mrow;
            int c = wn + nt * 8 + ncol;
            float b0 = bias[bn + c], b1 = bias[bn + c + 1];
            smc[r * 132 + c]             = acc[mt][nt][0] + b0;
            smc[r * 132 + c + 1]         = acc[mt][nt][1] + b1;
            smc[(r + 8) * 132 + c]       = acc[mt][nt][2] + b0;
            smc[(r + 8) * 132 + c + 1]   = acc[mt][nt][3] + b1;
        }
    }
    __syncthreads();

    int row = tid >> 1, half = tid & 1;
    const float* lr = smc + row * 132 + half * 64;
    float m = -3.4e38f, s = 0.f;
    #pragma unroll 8
    for (int c = 0; c < 64; c++) {
        float x = lr[c];
        float nm = fmaxf(m, x);
        s = s * __expf(m - nm) + __expf(x - nm);
        m = nm;
    }
    float m2 = __shfl_xor_sync(0xFFFFFFFF, m, 1);
    float s2 = __shfl_xor_sync(0xFFFFFFFF, s, 1);
    float M = fmaxf(m, m2);
    float S = s * __expf(m - M) + s2 * __expf(m2 - M);
    int grow = bm + row;
    if (half == 0) {
        d_pmax[(size_t)grow * NCB + blockIdx.x] = M;
        d_psum[(size_t)grow * NCB + blockIdx.x] = S;
        int target = ys[grow];
        if (target >= bn && target < bn + 128)
            d_tlogit[grow] = smc[row * 132 + (target - bn)];
    }
}

__global__ void nll_reduce_kernel(float* __restrict__ rownll) {
    int row = blockIdx.x * 256 + threadIdx.x;
    const float* pm = d_pmax + (size_t)row * NCB;
    const float* ps = d_psum + (size_t)row * NCB;
    float m = -3.4e38f, s = 0.f;
    #pragma unroll 8
    for (int c = 0; c < NCB; c++) {
        float m2 = pm[c], s2 = ps[c];
        float M = fmaxf(m, m2);
        s = s * __expf(m - M) + s2 * __expf(m2 - M);
        m = M;
    }
    rownll[row] = -(d_tlogit[row] - m - logf(s));
}

__global__ void mean_kernel(const float* __restrict__ rownll, float* __restrict__ out) {
    __shared__ float sred[256];
    int tid = threadIdx.x;
    float s = 0.f;
    for (int i = tid; i < B_*T_; i += 256) s += rownll[i];
    sred[tid] = s; __syncthreads();
    for (int k = 128; k > 0; k >>= 1) {
        if (tid < k) sred[tid] += sred[tid + k];
        __syncthreads();
    }
    if (tid == 0) out[0] = sred[0] / (float)(B_*T_);
}

// ---------------- persistent recurrence (exact R12-proven structure) ----------------
__global__ void reset_bar_kernel() { g_barcnt = 0u; }

__device__ __forceinline__ void gbar(unsigned target) {
    __syncthreads();
    if (threadIdx.x == 0) {
        asm volatile("red.release.gpu.global.add.u32 [%0], %1;"
                     :: "l"(&g_barcnt), "r"(1u) : "memory");
        unsigned v;
        do {
            asm volatile("ld.acquire.gpu.global.u32 %0, [%1];"
                         : "=r"(v) : "l"(&g_barcnt) : "memory");
        } while (v < target);
    }
    __syncthreads();
}

#define S_WBHI  0
#define S_WBLO  65536
#define S_WAHI  131072
#define S_WALO  147456
#define S_STG   163840
#define RS_BYTES 229376

__global__ void __launch_bounds__(256) recur_kernel(
    const float* __restrict__ zx, const float* __restrict__ mxp,
    const float* __restrict__ wmhnT, const float* __restrict__ whnT,
    __nv_bfloat16* __restrict__ hshi)
{
    extern __shared__ char smc[];
    float* stg = (float*)(smc + S_STG);
    const uint32_t sbase = smem_u32(smc);
    const int bk = blockIdx.x, tid = threadIdx.x;

    #pragma unroll 4
    for (int p = 0; p < 32; p++) {
        int col = (p >> 3) * H_ + bk * 8 + (p & 7);
        float4 v = ((const float4*)(whnT + (size_t)col * H_))[tid];
        __nv_bfloat16 hx = __float2bfloat16(v.x), hy = __float2bfloat16(v.y);
        __nv_bfloat16 hz = __float2bfloat16(v.z), hw = __float2bfloat16(v.w);
        __nv_bfloat16 lx = __float2bfloat16(v.x - __bfloat162float(hx));
        __nv_bfloat16 ly = __float2bfloat16(v.y - __bfloat162float(hy));
        __nv_bfloat16 lz = __float2bfloat16(v.z - __bfloat162float(hz));
        __nv_bfloat16 lw = __float2bfloat16(v.w - __bfloat162float(hw));
        uint32_t off = p * 2048 + ((tid * 8) ^ ((p & 7) * 16));
        *(uint2*)(smc + S_WBHI + off) = make_uint2(pk(hx, hy), pk(hz, hw));
        *(uint2*)(smc + S_WBLO + off) = make_uint2(pk(lx, ly), pk(lz, lw));
    }
    #pragma unroll
    for (int p = 0; p < 8; p++) {
        int col = bk * 8 + p;
        float4 v = ((const float4*)(wmhnT + (size_t)col * H_))[tid];
        __nv_bfloat16 hx = __float2bfloat16(v.x), hy = __float2bfloat16(v.y);
        __nv_bfloat16 hz = __float2bfloat16(v.z), hw = __float2bfloat16(v.w);
        __nv_bfloat16 lx = __float2bfloat16(v.x - __bfloat162float(hx));
        __nv_bfloat16 ly = __float2bfloat16(v.y - __bfloat162float(hy));
        __nv_bfloat16 lz = __float2bfloat16(v.z - __bfloat162float(hz));
        __nv_bfloat16 lw = __float2bfloat16(v.w - __bfloat162float(hw));
        uint32_t off = p * 2048 + ((tid * 8) ^ (p * 16));
        *(uint2*)(smc + S_WAHI + off) = make_uint2(pk(hx, hy), pk(hz, hw));
        *(uint2*)(smc + S_WALO + off) = make_uint2(pk(lx, ly), pk(lz, lw));
    }
    if (tid < 128) {
        int b = tid >> 3, col = bk*8 + (tid & 7);
        ((short*)d_hhi)[b*H_ + col] = 0;
        ((short*)d_hlo)[b*H_ + col] = 0;
    }
    unsigned tgt = NBLK;
    gbar(tgt); tgt += NBLK;

    const int l = tid & 31, wql = tid >> 5;
    const int arow = (l & 7) + ((l >> 3) & 1) * 8;
    const uint32_t ax = (uint32_t)((arow & 7) * 16);
    const uint32_t asel = ((uint32_t)(l >> 4)) << 4;
    const int brow7 = l & 7;
    const uint32_t bx = (uint32_t)(brow7 * 16);
    const uint32_t bsel = ((uint32_t)((l >> 3) & 1)) << 4;
    int rci[2], rb[2]; size_t rzoff[2];
    #pragma unroll
    for (int o = 0; o < 2; o++) {
        int out = tid + o*256;
        rci[o] = out >> 4; rb[o] = out & 15;
        int q = rci[o] >> 3, j0 = rci[o] & 7;
        rzoff[o] = (size_t)rb[o]*T_*FH + (size_t)q*H_ + bk*8 + j0;
    }
    const int bG = tid >> 3, j0G = tid & 7;
    float creg = 0.f;

    for (int t = 0; t < T_; t++) {
        float zpre0 = __ldg(&zx[rzoff[0] + (size_t)t*FH]);
        float zpre1 = __ldg(&zx[rzoff[1] + (size_t)t*FH]);
        float mxv = 0.f;
        if (tid < 128) mxv = __ldg(&mxp[(size_t)(bG*T_ + t)*H_ + bk*8 + j0G]);

        {   // stage h (block-cooperative, proven)
            #pragma unroll
            for (int p = 0; p < 16; p++) {
                int i = tid + p * 256;
                int half = i >> 11, j = i & 2047;
                int b = j >> 7, c = j & 127;
                const uint4* src = (const uint4*)(half ? d_hlo : d_hhi);
                uint4 v = __ldcg(src + j);
                *(uint4*)(smc + S_STG + half*32768 + b*2048 + ((c*16) ^ ((b&7)*16))) = v;
            }
        }
        __syncthreads();

        // phase A
        float accA[4] = {0.f, 0.f, 0.f, 0.f};
        #pragma unroll
        for (int kc = 0; kc < 8; kc++) {
            uint32_t kb = (uint32_t)(wql*256 + kc*32);
            uint32_t aaddr = sbase + S_STG + (uint32_t)arow*2048 + ((kb + asel) ^ ax);
            uint32_t ah[4], al[4];
            ldm_x4(ah, aaddr);
            ldm_x4(al, aaddr + 32768);
            uint32_t bkb = (kb + bsel) ^ bx;
            uint32_t baddr = sbase + S_WAHI + (uint32_t)brow7*2048 + bkb;
            uint32_t bh2[2], bl2[2];
            ldm_x2(bh2, baddr);
            ldm_x2(bl2, baddr + 16384);
            mma_bf16(accA, ah, bh2);
            mma_bf16(accA, ah, bl2);
            mma_bf16(accA, al, bh2);
        }
        __syncthreads();
        {
            int bq = l >> 2, cq = (l & 3) * 2;
            stg[(cq*16 + bq)*9 + wql]           = accA[0];
            stg[((cq+1)*16 + bq)*9 + wql]       = accA[1];
            stg[(cq*16 + bq + 8)*9 + wql]       = accA[2];
            stg[((cq+1)*16 + bq + 8)*9 + wql]   = accA[3];
        }
        __syncthreads();
        if (tid < 128) {
            const float* pp = stg + (j0G*16 + bG)*9;
            float s = ((pp[0]+pp[1]) + (pp[2]+pp[3])) + ((pp[4]+pp[5]) + (pp[6]+pp[7]));
            float mval = s * mxv;
            __nv_bfloat16 mh = __float2bfloat16(mval);
            __nv_bfloat16 ml = __float2bfloat16(mval - __bfloat162float(mh));
            __stcg((short*)&d_mthi[bG*H_ + bk*8 + j0G], *(short*)&mh);
            __stcg((short*)&d_mtlo[bG*H_ + bk*8 + j0G], *(short*)&ml);
        }
        gbar(tgt); tgt += NBLK;

        {   // stage m
            #pragma unroll
            for (int p = 0; p < 16; p++) {
                int i = tid + p * 256;
                int half = i >> 11, j = i & 2047;
                int b = j >> 7, c = j & 127;
                const uint4* src = (const uint4*)(half ? d_mtlo : d_mthi);
                uint4 v = __ldcg(src + j);
                *(uint4*)(smc + S_STG + half*32768 + b*2048 + ((c*16) ^ ((b&7)*16))) = v;
            }
        }
        __syncthreads();

        // phase B
        float acc[4][4];
        #pragma unroll
        for (int nt = 0; nt < 4; nt++)
            #pragma unroll
            for (int u = 0; u < 4; u++) acc[nt][u] = 0.f;
        #pragma unroll
        for (int kc = 0; kc < 8; kc++) {
            uint32_t kb = (uint32_t)(wql*256 + kc*32);
            uint32_t aaddr = sbase + S_STG + (uint32_t)arow*2048 + ((kb + asel) ^ ax);
            uint32_t ah[4], al[4];
            ldm_x4(ah, aaddr);
            ldm_x4(al, aaddr + 32768);
            uint32_t bkb = (kb + bsel) ^ bx;
            #pragma unroll
            for (int nt = 0; nt < 4; nt++) {
                uint32_t baddr = sbase + S_WBHI + (uint32_t)(nt*8 + brow7)*2048 + bkb;
                uint32_t bh[2], bl[2];
                ldm_x2(bh, baddr);
                ldm_x2(bl, baddr + 65536);
                mma_bf16(acc[nt], ah, bh);
                mma_bf16(acc[nt], ah, bl);
                mma_bf16(acc[nt], al, bh);
            }
        }
        __syncthreads();
        {
            int bq = l >> 2, cq = (l & 3) * 2;
            #pragma unroll
            for (int nt = 0; nt < 4; nt++) {
                int c0 = nt*8 + cq;
                stg[(c0*16 + bq)*9 + wql]          = acc[nt][0];
                stg[((c0+1)*16 + bq)*9 + wql]      = acc[nt][1];
                stg[(c0*16 + bq + 8)*9 + wql]      = acc[nt][2];
                stg[((c0+1)*16 + bq + 8)*9 + wql]  = acc[nt][3];
            }
        }
        __syncthreads();

        {
            const float* p0 = stg + (rci[0]*16 + rb[0])*9;
            float s0 = ((p0[0]+p0[1]) + (p0[2]+p0[3])) + ((p0[4]+p0[5]) + (p0[6]+p0[7]));
            stg[8192 + rb[0]*32 + rci[0]] = zpre0 + s0;
            const float* p1 = stg + (rci[1]*16 + rb[1])*9;
            float s1 = ((p1[0]+p1[1]) + (p1[2]+p1[3])) + ((p1[4]+p1[5]) + (p1[6]+p1[7]));
            stg[8192 + rb[1]*32 + rci[1]] = zpre1 + s1;
        }
        __syncthreads();

        if (tid < 128) {
            float zi = stg[8192 + bG*32 +      j0G];
            float zf = stg[8192 + bG*32 +  8 + j0G];
            float zo = stg[8192 + bG*32 + 16 + j0G];
            float zu = stg[8192 + bG*32 + 24 + j0G];
            float ig = 1.f / (1.f + expf(-zi));
            float fg = 1.f / (1.f + expf(-zf));
            float og = 1.f / (1.f + expf(-zo));
            float ug = tanhf(zu);
            creg = fg * creg + ig * ug;
            float h = og * tanhf(creg);
            int col = bk*8 + j0G;
            __nv_bfloat16 hh = __float2bfloat16(h);
            __nv_bfloat16 hl = __float2bfloat16(h - __bfloat162float(hh));
            __stcg((short*)&d_hhi[bG*H_ + col], *(short*)&hh);
            __stcg((short*)&d_hlo[bG*H_ + col], *(short*)&hl);
            hshi[(size_t)(bG*T_ + t)*H_ + col] = hh;
        }
        gbar(tgt); tgt += NBLK;
    }
}

// ---------------- launcher ----------------
extern "C" void kernel_launch(void* const* d_in, const int* in_sizes, int n_in,
                              void* d_out, int out_size) {
    (void)in_sizes; (void)n_in; (void)out_size;
    const int*   xs      = (const int*)  d_in[0];
    const int*   ys      = (const int*)  d_in[1];
    const float* embed_w = (const float*)d_in[2];
    const float* wx      = (const float*)d_in[3];
    const float* wh      = (const float*)d_in[4];
    const float* wmx     = (const float*)d_in[5];
    const float* wmh     = (const float*)d_in[6];
    const float* bb      = (const float*)d_in[7];
    const float* gx      = (const float*)d_in[8];
    const float* gh      = (const float*)d_in[9];
    const float* gmx     = (const float*)d_in[10];
    const float* gmh     = (const float*)d_in[11];
    const float* pred_w  = (const float*)d_in[12];
    const float* pred_b  = (const float*)d_in[13];
    float* out = (float*)d_out;

    float *p_whnT, *p_wmhnT, *p_zx, *p_mx, *p_rownll;
    float *p_nwx, *p_nwh, *p_nwmx, *p_nwmh;
    __nv_bfloat16 *p_xhi, *p_xlo, *p_wxnThi, *p_wxnTlo, *p_wmxnThi, *p_wmxnTlo;
    __nv_bfloat16 *p_pwhi, *p_hshi;
    cudaGetSymbolAddress((void**)&p_whnT,    d_whnT);
    cudaGetSymbolAddress((void**)&p_wmhnT,   d_wmhnT);
    cudaGetSymbolAddress((void**)&p_zx,      d_zx);
    cudaGetSymbolAddress((void**)&p_mx,      d_mx);
    cudaGetSymbolAddress((void**)&p_rownll,  d_rownll);
    cudaGetSymbolAddress((void**)&p_nwx,     d_nwx);
    cudaGetSymbolAddress((void**)&p_nwh,     d_nwh);
    cudaGetSymbolAddress((void**)&p_nwmx,    d_nwmx);
    cudaGetSymbolAddress((void**)&p_nwmh,    d_nwmh);
    cudaGetSymbolAddress((void**)&p_xhi,     d_xhi);
    cudaGetSymbolAddress((void**)&p_xlo,     d_xlo);
    cudaGetSymbolAddress((void**)&p_wxnThi,  d_wxnThi);
    cudaGetSymbolAddress((void**)&p_wxnTlo,  d_wxnTlo);
    cudaGetSymbolAddress((void**)&p_wmxnThi, d_wmxnThi);
    cudaGetSymbolAddress((void**)&p_wmxnTlo, d_wmxnTlo);
    cudaGetSymbolAddress((void**)&p_pwhi,    d_pwhi);
    cudaGetSymbolAddress((void**)&p_hshi,    d_hshi);

    static bool attr_set = false;
    if (!attr_set) {
        cudaFuncSetAttribute(recur_kernel, cudaFuncAttributeMaxDynamicSharedMemorySize, RS_BYTES);
        cudaFuncSetAttribute(mma_gemm<true, false>, cudaFuncAttributeMaxDynamicSharedMemorySize, GSMEM);
        cudaFuncSetAttribute(mma_gemm<false, true>, cudaFuncAttributeMaxDynamicSharedMemorySize, GSMEM);
        cudaFuncSetAttribute(logits_nll_kernel, cudaFuncAttributeMaxDynamicSharedMemorySize, GSMEM);
        attr_set = true;
    }

    // weight norm (fused sumsq over all 4 matrices)
    zero_norms_kernel<<<16, 256>>>();
    sumsq4_kernel<<<dim3(16, 4, 32), 256>>>(wx, wh, wmx, wmh);
    scaleT_bf16_kernel<<<dim3(FH/32, E_/32), dim3(32,8)>>>(wx,  gx,  p_nwx,  p_wxnThi,  p_wxnTlo,  E_, FH);
    scaleT_bf16_kernel<<<dim3(H_/32, E_/32), dim3(32,8)>>>(wmx, gmx, p_nwmx, p_wmxnThi, p_wmxnTlo, E_, H_);
    scaleT_kernel<<<dim3(FH/32, H_/32), dim3(32,8)>>>(wh,  gh,  p_nwh,  p_whnT,  H_, FH);
    scaleT_kernel<<<dim3(H_/32, H_/32), dim3(32,8)>>>(wmh, gmh, p_nwmh, p_wmhnT, H_, H_);
    split_hi_kernel<<<(int)(((size_t)V_*H_ + 255)/256), 256>>>(pred_w, p_pwhi, (size_t)V_*H_);

    // embedding
    embed_kernel<<<B_*T_, 128>>>(xs, embed_w, p_xhi, p_xlo);

    // input projections: zx 2-pass (additive path), mx 3-pass (recurrent path)
    mma_gemm<true,  false><<<dim3(FH/128, (B_*T_)/128), 256, GSMEM>>>(
        p_xhi, p_xlo, p_wxnThi, p_wxnTlo, bb, p_zx, B_*T_, FH, E_);
    mma_gemm<false, true ><<<dim3(H_/128, (B_*T_)/128), 256, GSMEM>>>(
        p_xhi, p_xlo, p_wmxnThi, p_wmxnTlo, (const float*)nullptr, p_mx, B_*T_, H_, E_);

    // recurrence (R12-proven)
    reset_bar_kernel<<<1, 1>>>();
    recur_kernel<<<NBLK, 256, RS_BYTES>>>(
        p_zx, p_mx, p_wmhnT, p_whnT, p_hshi);

    // fused logits (1-pass bf16) + softmax partials + loss
    logits_nll_kernel<<<dim3(NCB, (B_*T_)/128), 256, GSMEM>>>(
        p_hshi, p_pwhi, pred_b, ys);
    nll_reduce_kernel<<<(B_*T_)/256, 256>>>(p_rownll);
    mean_kernel<<<1, 256>>>(p_rownll, out);
}

// round 15
// speedup vs baseline: 1.4295x; 1.1259x over previous
#include <cuda_runtime.h>
#include <cuda_bf16.h>
#include <cstdint>

#define B_  16
#define T_  512
#define V_  8192
#define E_  512
#define H_  1024
#define FH  4096
#define NBLK 128
#define NCB (V_/128)        // 64 column-blocks for logits

// ---------------- device scratch ----------------
__device__ __nv_bfloat16 d_xhi[B_*T_*E_], d_xlo[B_*T_*E_];
__device__ __nv_bfloat16 d_wxnThi[(size_t)FH*E_], d_wxnTlo[(size_t)FH*E_];
__device__ __nv_bfloat16 d_wmxnThi[H_*E_], d_wmxnTlo[H_*E_];
__device__ __nv_bfloat16 d_pwhi[(size_t)V_*H_];
__device__ __nv_bfloat16 d_hshi[B_*T_*H_];
__device__ float d_whnT[(size_t)FH*H_];
__device__ float d_wmhnT[H_*H_];
__device__ float d_nwx[FH], d_nwh[FH], d_nwmx[H_], d_nwmh[H_];
__device__ float d_zx[(size_t)B_*T_*FH];
__device__ float d_mx[B_*T_*H_];
__device__ __nv_bfloat16 d_hhi[B_*H_];
__device__ __nv_bfloat16 d_mthi[B_*H_];
__device__ float d_pmax[(size_t)B_*T_*NCB];
__device__ float d_psum[(size_t)B_*T_*NCB];
__device__ float d_tlogit[B_*T_];
__device__ float d_rownll[B_*T_];
__device__ unsigned g_barcnt;

// ---------------- helpers ----------------
__device__ __forceinline__ uint32_t smem_u32(const void* p) {
    uint32_t a;
    asm("{ .reg .u64 t; cvta.to.shared.u64 t, %1; cvt.u32.u64 %0, t; }" : "=r"(a) : "l"(p));
    return a;
}
__device__ __forceinline__ void ldm_x4(uint32_t* r, uint32_t addr) {
    asm volatile("ldmatrix.sync.aligned.m8n8.x4.shared.b16 {%0,%1,%2,%3}, [%4];"
                 : "=r"(r[0]), "=r"(r[1]), "=r"(r[2]), "=r"(r[3]) : "r"(addr));
}
__device__ __forceinline__ void ldm_x2(uint32_t* r, uint32_t addr) {
    asm volatile("ldmatrix.sync.aligned.m8n8.x2.shared.b16 {%0,%1}, [%2];"
                 : "=r"(r[0]), "=r"(r[1]) : "r"(addr));
}
__device__ __forceinline__ void mma_bf16(float* c, const uint32_t* a, const uint32_t* b) {
    asm volatile("mma.sync.aligned.m16n8k16.row.col.f32.bf16.bf16.f32 "
                 "{%0,%1,%2,%3}, {%4,%5,%6,%7}, {%8,%9}, {%0,%1,%2,%3};"
                 : "+f"(c[0]), "+f"(c[1]), "+f"(c[2]), "+f"(c[3])
                 : "r"(a[0]), "r"(a[1]), "r"(a[2]), "r"(a[3]), "r"(b[0]), "r"(b[1]));
}
__device__ __forceinline__ uint32_t pk(__nv_bfloat16 a, __nv_bfloat16 b) {
    __nv_bfloat162 t = __halves2bfloat162(a, b);
    return *(uint32_t*)&t;
}
__device__ __forceinline__ void cpa16(uint32_t saddr, const void* g) {
    asm volatile("cp.async.cg.shared.global [%0], [%1], 16;" :: "r"(saddr), "l"(g) : "memory");
}

// ---------------- weight norm ----------------
__global__ void zero_norms_kernel() {
    int i = blockIdx.x * 256 + threadIdx.x;
    if (i < FH) { d_nwx[i] = 0.f; d_nwh[i] = 0.f; }
    if (i < H_) { d_nwmx[i] = 0.f; d_nwmh[i] = 0.f; }
}
__global__ void sumsq4_kernel(const float* __restrict__ wx, const float* __restrict__ wh,
                              const float* __restrict__ wmx, const float* __restrict__ wmh) {
    int id = blockIdx.y;
    const float* w; float* nrm; int K, N;
    if (id == 0)      { w = wx;  nrm = d_nwx;  K = E_; N = FH; }
    else if (id == 1) { w = wh;  nrm = d_nwh;  K = H_; N = FH; }
    else if (id == 2) { w = wmx; nrm = d_nwmx; K = E_; N = H_; }
    else              { w = wmh; nrm = d_nwmh; K = H_; N = H_; }
    int j = blockIdx.x * 256 + threadIdx.x;
    int k0 = blockIdx.z * 32;
    if (j >= N || k0 >= K) return;
    float ss = 0.f;
    #pragma unroll 4
    for (int k = k0; k < k0 + 32; k++) { float v = w[(size_t)k*N + j]; ss += v*v; }
    atomicAdd(&nrm[j], ss);
}
__global__ void scaleT_kernel(const float* __restrict__ w, const float* __restrict__ g,
                              const float* __restrict__ nrm, float* __restrict__ out,
                              int K, int N) {
    __shared__ float tile[32][33];
    int n0 = blockIdx.x * 32, k0 = blockIdx.y * 32;
    int tx = threadIdx.x, ty = threadIdx.y;
    for (int r = ty; r < 32; r += 8)
        tile[r][tx] = w[(size_t)(k0 + r)*N + n0 + tx];
    __syncthreads();
    for (int r = ty; r < 32; r += 8) {
        int n = n0 + r;
        float s = g[n] / fmaxf(sqrtf(nrm[n]), 1e-12f);
        out[(size_t)n*K + k0 + tx] = tile[tx][r] * s;
    }
}
__global__ void scaleT_bf16_kernel(const float* __restrict__ w, const float* __restrict__ g,
                                   const float* __restrict__ nrm,
                                   __nv_bfloat16* __restrict__ ohi,
                                   __nv_bfloat16* __restrict__ olo,
                                   int K, int N) {
    __shared__ float tile[32][33];
    int n0 = blockIdx.x * 32, k0 = blockIdx.y * 32;
    int tx = threadIdx.x, ty = threadIdx.y;
    for (int r = ty; r < 32; r += 8)
        tile[r][tx] = w[(size_t)(k0 + r)*N + n0 + tx];
    __syncthreads();
    for (int r = ty; r < 32; r += 8) {
        int n = n0 + r;
        float s = g[n] / fmaxf(sqrtf(nrm[n]), 1e-12f);
        float v = tile[tx][r] * s;
        __nv_bfloat16 hi = __float2bfloat16(v);
        ohi[(size_t)n*K + k0 + tx] = hi;
        olo[(size_t)n*K + k0 + tx] = __float2bfloat16(v - __bfloat162float(hi));
    }
}
__global__ void split_hi_kernel(const float* __restrict__ w,
                                __nv_bfloat16* __restrict__ ohi, size_t total) {
    size_t i = (size_t)blockIdx.x * 256 + threadIdx.x;
    if (i >= total) return;
    ohi[i] = __float2bfloat16(w[i]);
}

// ---------------- embedding ----------------
__global__ void embed_kernel(const int* __restrict__ xs, const float* __restrict__ ew,
                             __nv_bfloat16* __restrict__ xhi, __nv_bfloat16* __restrict__ xlo) {
    int r = blockIdx.x;
    int idx = xs[r];
    const float4* src = (const float4*)(ew + (size_t)idx * E_);
    float4 v = src[threadIdx.x];
    if (idx == 0) v = make_float4(0.f, 0.f, 0.f, 0.f);
    size_t base = (size_t)r * E_ + threadIdx.x * 4;
    float vv[4] = {v.x, v.y, v.z, v.w};
    #pragma unroll
    for (int u = 0; u < 4; u++) {
        __nv_bfloat16 hi = __float2bfloat16(vv[u]);
        xhi[base + u] = hi;
        xlo[base + u] = __float2bfloat16(vv[u] - __bfloat162float(hi));
    }
}

// ---------------- mma.sync split-bf16 GEMM cores ----------------
#define GSMEM 131072

template<bool THIRD>
__device__ __forceinline__ void gemm_main3(
    char* smem, uint32_t sbase,
    const __nv_bfloat16* Ahi, const __nv_bfloat16* Alo,
    const __nv_bfloat16* Bhi, const __nv_bfloat16* Blo,
    int bm, int bn, int K, float acc[4][4][4])
{
    const int tid = threadIdx.x, lid = tid & 31, wid = tid >> 5;
    const int wm = (wid & 1) * 64, wn = (wid >> 1) * 32;
    #pragma unroll
    for (int mt = 0; mt < 4; mt++)
        #pragma unroll
        for (int nt = 0; nt < 4; nt++)
            #pragma unroll
            for (int u = 0; u < 4; u++) acc[mt][nt][u] = 0.f;

    auto issue = [&](int ch, int buf) {
        int k0 = ch << 6;
        #pragma unroll
        for (int p = 0; p < 16; p++) {
            int i = tid + p * 256;
            int tile = i >> 10, j = i & 1023;
            int row = j >> 3, c = j & 7;
            const __nv_bfloat16* src = (tile == 0) ? Ahi : (tile == 1) ? Alo
                                     : (tile == 2) ? Bhi : Blo;
            int grow = ((tile < 2) ? bm : bn) + row;
            uint32_t sa = sbase + (uint32_t)buf*65536 + tile*16384
                        + (row * 8 + (c ^ (row & 7))) * 16;
            cpa16(sa, src + (size_t)grow * K + k0 + c * 8);
        }
        asm volatile("cp.async.commit_group;" ::: "memory");
    };

    const int nchunk = K >> 6;
    issue(0, 0);
    for (int ch = 0; ch < nchunk; ch++) {
        if (ch + 1 < nchunk) {
            issue(ch + 1, (ch + 1) & 1);
            asm volatile("cp.async.wait_group 1;" ::: "memory");
        } else {
            asm volatile("cp.async.wait_group 0;" ::: "memory");
        }
        __syncthreads();
        const uint32_t boff = sbase + (uint32_t)((ch & 1) * 65536);
        #pragma unroll
        for (int ks = 0; ks < 4; ks++) {
            uint32_t bh[4][2], bl[4][2];
            {
                int row = wn + (lid & 7);
                int cc = 2 * ks + ((lid >> 3) & 1);
                #pragma unroll
                for (int nt = 0; nt < 4; nt++) {
                    int r = row + nt * 8;
                    uint32_t addr = boff + 32768 + (r * 8 + (cc ^ (r & 7))) * 16;
                    ldm_x2(bh[nt], addr);
                    ldm_x2(bl[nt], addr + 16384);
                }
            }
            #pragma unroll
            for (int mt = 0; mt < 4; mt++) {
                int r = wm + mt * 16 + (lid & 7) + ((lid >> 3) & 1) * 8;
                int cc = 2 * ks + (lid >> 4);
                uint32_t addr = boff + (r * 8 + (cc ^ (r & 7))) * 16;
                uint32_t ah[4], al[4];
                ldm_x4(ah, addr);
                ldm_x4(al, addr + 16384);
                #pragma unroll
                for (int nt = 0; nt < 4; nt++) {
                    mma_bf16(acc[mt][nt], ah, bh[nt]);
                    mma_bf16(acc[mt][nt], ah, bl[nt]);
                    if (THIRD) mma_bf16(acc[mt][nt], al, bh[nt]);
                }
            }
        }
        __syncthreads();
    }
}

__device__ __forceinline__ void gemm_main1(
    char* smem, uint32_t sbase,
    const __nv_bfloat16* Ahi, const __nv_bfloat16* Bhi,
    int bm, int bn, int K, float acc[4][4][4])
{
    const int tid = threadIdx.x, lid = tid & 31, wid = tid >> 5;
    const int wm = (wid & 1) * 64, wn = (wid >> 1) * 32;
    #pragma unroll
    for (int mt = 0; mt < 4; mt++)
        #pragma unroll
        for (int nt = 0; nt < 4; nt++)
            #pragma unroll
            for (int u = 0; u < 4; u++) acc[mt][nt][u] = 0.f;

    auto issue = [&](int ch, int buf) {
        int k0 = ch << 6;
        #pragma unroll
        for (int p = 0; p < 8; p++) {
            int i = tid + p * 256;
            int tile = i >> 10, j = i & 1023;
            int row = j >> 3, c = j & 7;
            const __nv_bfloat16* src = (tile == 0) ? Ahi : Bhi;
            int grow = ((tile == 0) ? bm : bn) + row;
            uint32_t sa = sbase + (uint32_t)buf*32768 + tile*16384
                        + (row * 8 + (c ^ (row & 7))) * 16;
            cpa16(sa, src + (size_t)grow * K + k0 + c * 8);
        }
        asm volatile("cp.async.commit_group;" ::: "memory");
    };

    const int nchunk = K >> 6;
    issue(0, 0);
    for (int ch = 0; ch < nchunk; ch++) {
        if (ch + 1 < nchunk) {
            issue(ch + 1, (ch + 1) & 1);
            asm volatile("cp.async.wait_group 1;" ::: "memory");
        } else {
            asm volatile("cp.async.wait_group 0;" ::: "memory");
        }
        __syncthreads();
        const uint32_t boff = sbase + (uint32_t)((ch & 1) * 32768);
        #pragma unroll
        for (int ks = 0; ks < 4; ks++) {
            uint32_t bh[4][2];
            {
                int row = wn + (lid & 7);
                int cc = 2 * ks + ((lid >> 3) & 1);
                #pragma unroll
                for (int nt = 0; nt < 4; nt++) {
                    int r = row + nt * 8;
                    ldm_x2(bh[nt], boff + 16384 + (r * 8 + (cc ^ (r & 7))) * 16);
                }
            }
            #pragma unroll
            for (int mt = 0; mt < 4; mt++) {
                int r = wm + mt * 16 + (lid & 7) + ((lid >> 3) & 1) * 8;
                int cc = 2 * ks + (lid >> 4);
                uint32_t ah[4];
                ldm_x4(ah, boff + (r * 8 + (cc ^ (r & 7))) * 16);
                #pragma unroll
                for (int nt = 0; nt < 4; nt++)
                    mma_bf16(acc[mt][nt], ah, bh[nt]);
            }
        }
        __syncthreads();
    }
}

template<bool BIAS, bool THIRD>
__global__ void __launch_bounds__(256) mma_gemm(
    const __nv_bfloat16* __restrict__ Ahi, const __nv_bfloat16* __restrict__ Alo,
    const __nv_bfloat16* __restrict__ Bhi, const __nv_bfloat16* __restrict__ Blo,
    const float* __restrict__ bias, float* __restrict__ C,
    int M, int N, int K)
{
    extern __shared__ char smem[];
    const uint32_t sbase = smem_u32(smem);
    const int tid = threadIdx.x, lid = tid & 31, wid = tid >> 5;
    const int wm = (wid & 1) * 64, wn = (wid >> 1) * 32;
    const int bn = blockIdx.x * 128, bm = blockIdx.y * 128;
    float acc[4][4][4];
    gemm_main3<THIRD>(smem, sbase, Ahi, Alo, Bhi, Blo, bm, bn, K, acc);

    const int mrow = (lid >> 2), ncol = (lid & 3) * 2;
    #pragma unroll
    for (int mt = 0; mt < 4; mt++) {
        #pragma unroll
        for (int nt = 0; nt < 4; nt++) {
            int row0 = bm + wm + mt * 16 + mrow;
            int col = bn + wn + nt * 8 + ncol;
            float2 v0 = make_float2(acc[mt][nt][0], acc[mt][nt][1]);
            float2 v1 = make_float2(acc[mt][nt][2], acc[mt][nt][3]);
            if (BIAS) {
                float b0 = bias[col], b1 = bias[col + 1];
                v0.x += b0; v0.y += b1;
                v1.x += b0; v1.y += b1;
            }
            *(float2*)&C[(size_t)row0 * N + col] = v0;
            *(float2*)&C[(size_t)(row0 + 8) * N + col] = v1;
        }
    }
}

// ---------------- fused logits (1-pass bf16) + online-softmax partials ----------------
__global__ void __launch_bounds__(256) logits_nll_kernel(
    const __nv_bfloat16* __restrict__ Ahi,
    const __nv_bfloat16* __restrict__ Bhi,
    const float* __restrict__ bias, const int* __restrict__ ys)
{
    extern __shared__ char smem[];
    const uint32_t sbase = smem_u32(smem);
    const int tid = threadIdx.x, lid = tid & 31, wid = tid >> 5;
    const int wm = (wid & 1) * 64, wn = (wid >> 1) * 32;
    const int bn = blockIdx.x * 128, bm = blockIdx.y * 128;
    float acc[4][4][4];
    gemm_main1(smem, sbase, Ahi, Bhi, bm, bn, H_, acc);

    float* smc = (float*)smem;
    const int mrow = (lid >> 2), ncol = (lid & 3) * 2;
    #pragma unroll
    for (int mt = 0; mt < 4; mt++) {
        #pragma unroll
        for (int nt = 0; nt < 4; nt++) {
            int r = wm + mt * 16 + mrow;
            int c = wn + nt * 8 + ncol;
            float b0 = bias[bn + c], b1 = bias[bn + c + 1];
            smc[r * 132 + c]             = acc[mt][nt][0] + b0;
            smc[r * 132 + c + 1]         = acc[mt][nt][1] + b1;
            smc[(r + 8) * 132 + c]       = acc[mt][nt][2] + b0;
            smc[(r + 8) * 132 + c + 1]   = acc[mt][nt][3] + b1;
        }
    }
    __syncthreads();

    int row = tid >> 1, half = tid & 1;
    const float* lr = smc + row * 132 + half * 64;
    float m = -3.4e38f, s = 0.f;
    #pragma unroll 8
    for (int c = 0; c < 64; c++) {
        float x = lr[c];
        float nm = fmaxf(m, x);
        s = s * __expf(m - nm) + __expf(x - nm);
        m = nm;
    }
    float m2 = __shfl_xor_sync(0xFFFFFFFF, m, 1);
    float s2 = __shfl_xor_sync(0xFFFFFFFF, s, 1);
    float M = fmaxf(m, m2);
    float S = s * __expf(m - M) + s2 * __expf(m2 - M);
    int grow = bm + row;
    if (half == 0) {
        d_pmax[(size_t)grow * NCB + blockIdx.x] = M;
        d_psum[(size_t)grow * NCB + blockIdx.x] = S;
        int target = ys[grow];
        if (target >= bn && target < bn + 128)
            d_tlogit[grow] = smc[row * 132 + (target - bn)];
    }
}

__global__ void nll_reduce_kernel(float* __restrict__ rownll) {
    int row = blockIdx.x * 256 + threadIdx.x;
    const float* pm = d_pmax + (size_t)row * NCB;
    const float* ps = d_psum + (size_t)row * NCB;
    float m = -3.4e38f, s = 0.f;
    #pragma unroll 8
    for (int c = 0; c < NCB; c++) {
        float m2 = pm[c], s2 = ps[c];
        float M = fmaxf(m, m2);
        s = s * __expf(m - M) + s2 * __expf(m2 - M);
        m = M;
    }
    rownll[row] = -(d_tlogit[row] - m - logf(s));
}

__global__ void mean_kernel(const float* __restrict__ rownll, float* __restrict__ out) {
    __shared__ float sred[256];
    int tid = threadIdx.x;
    float s = 0.f;
    for (int i = tid; i < B_*T_; i += 256) s += rownll[i];
    sred[tid] = s; __syncthreads();
    for (int k = 128; k > 0; k >>= 1) {
        if (tid < k) sred[tid] += sred[tid + k];
        __syncthreads();
    }
    if (tid == 0) out[0] = sred[0] / (float)(B_*T_);
}

// ---------------- persistent recurrence: hi-only state, 2-pass phases ----------------
__global__ void reset_bar_kernel() { g_barcnt = 0u; }

__device__ __forceinline__ void gbar(unsigned target) {
    __syncthreads();
    if (threadIdx.x == 0) {
        asm volatile("red.release.gpu.global.add.u32 [%0], %1;"
                     :: "l"(&g_barcnt), "r"(1u) : "memory");
        unsigned v;
        do {
            asm volatile("ld.acquire.gpu.global.u32 %0, [%1];"
                         : "=r"(v) : "l"(&g_barcnt) : "memory");
        } while (v < target);
    }
    __syncthreads();
}

#define S_WBHI  0
#define S_WBLO  65536
#define S_WAHI  131072
#define S_WALO  147456
#define S_STG   163840
#define RS_BYTES 229376

__global__ void __launch_bounds__(256) recur_kernel(
    const float* __restrict__ zx, const float* __restrict__ mxp,
    const float* __restrict__ wmhnT, const float* __restrict__ whnT,
    __nv_bfloat16* __restrict__ hshi)
{
    extern __shared__ char smc[];
    float* stg = (float*)(smc + S_STG);
    const uint32_t sbase = smem_u32(smc);
    const int bk = blockIdx.x, tid = threadIdx.x;

    #pragma unroll 4
    for (int p = 0; p < 32; p++) {
        int col = (p >> 3) * H_ + bk * 8 + (p & 7);
        float4 v = ((const float4*)(whnT + (size_t)col * H_))[tid];
        __nv_bfloat16 hx = __float2bfloat16(v.x), hy = __float2bfloat16(v.y);
        __nv_bfloat16 hz = __float2bfloat16(v.z), hw = __float2bfloat16(v.w);
        __nv_bfloat16 lx = __float2bfloat16(v.x - __bfloat162float(hx));
        __nv_bfloat16 ly = __float2bfloat16(v.y - __bfloat162float(hy));
        __nv_bfloat16 lz = __float2bfloat16(v.z - __bfloat162float(hz));
        __nv_bfloat16 lw = __float2bfloat16(v.w - __bfloat162float(hw));
        uint32_t off = p * 2048 + ((tid * 8) ^ ((p & 7) * 16));
        *(uint2*)(smc + S_WBHI + off) = make_uint2(pk(hx, hy), pk(hz, hw));
        *(uint2*)(smc + S_WBLO + off) = make_uint2(pk(lx, ly), pk(lz, lw));
    }
    #pragma unroll
    for (int p = 0; p < 8; p++) {
        int col = bk * 8 + p;
        float4 v = ((const float4*)(wmhnT + (size_t)col * H_))[tid];
        __nv_bfloat16 hx = __float2bfloat16(v.x), hy = __float2bfloat16(v.y);
        __nv_bfloat16 hz = __float2bfloat16(v.z), hw = __float2bfloat16(v.w);
        __nv_bfloat16 lx = __float2bfloat16(v.x - __bfloat162float(hx));
        __nv_bfloat16 ly = __float2bfloat16(v.y - __bfloat162float(hy));
        __nv_bfloat16 lz = __float2bfloat16(v.z - __bfloat162float(hz));
        __nv_bfloat16 lw = __float2bfloat16(v.w - __bfloat162float(hw));
        uint32_t off = p * 2048 + ((tid * 8) ^ (p * 16));
        *(uint2*)(smc + S_WAHI + off) = make_uint2(pk(hx, hy), pk(hz, hw));
        *(uint2*)(smc + S_WALO + off) = make_uint2(pk(lx, ly), pk(lz, lw));
    }
    if (tid < 128) {
        int b = tid >> 3, col = bk*8 + (tid & 7);
        ((short*)d_hhi)[b*H_ + col] = 0;
    }
    unsigned tgt = NBLK;
    gbar(tgt); tgt += NBLK;

    const int l = tid & 31, wql = tid >> 5;
    const int arow = (l & 7) + ((l >> 3) & 1) * 8;
    const uint32_t ax = (uint32_t)((arow & 7) * 16);
    const uint32_t asel = ((uint32_t)(l >> 4)) << 4;
    const int brow7 = l & 7;
    const uint32_t bx = (uint32_t)(brow7 * 16);
    const uint32_t bsel = ((uint32_t)((l >> 3) & 1)) << 4;
    int rci[2], rb[2]; size_t rzoff[2];
    #pragma unroll
    for (int o = 0; o < 2; o++) {
        int out = tid + o*256;
        rci[o] = out >> 4; rb[o] = out & 15;
        int q = rci[o] >> 3, j0 = rci[o] & 7;
        rzoff[o] = (size_t)rb[o]*T_*FH + (size_t)q*H_ + bk*8 + j0;
    }
    const int bG = tid >> 3, j0G = tid & 7;
    float creg = 0.f;

    for (int t = 0; t < T_; t++) {
        float zpre0 = __ldg(&zx[rzoff[0] + (size_t)t*FH]);
        float zpre1 = __ldg(&zx[rzoff[1] + (size_t)t*FH]);
        float mxv = 0.f;
        if (tid < 128) mxv = __ldg(&mxp[(size_t)(bG*T_ + t)*H_ + bk*8 + j0G]);

        {   // stage h (hi only: 32KB, 2048 16B-chunks)
            #pragma unroll
            for (int p = 0; p < 8; p++) {
                int j = tid + p * 256;
                int b = j >> 7, c = j & 127;
                uint4 v = __ldcg((const uint4*)d_hhi + j);
                *(uint4*)(smc + S_STG + b*2048 + ((c*16) ^ ((b&7)*16))) = v;
            }
        }
        __syncthreads();

        // phase A (2-pass: ah*bh + ah*bl)
        float accA[4] = {0.f, 0.f, 0.f, 0.f};
        #pragma unroll
        for (int kc = 0; kc < 8; kc++) {
            uint32_t kb = (uint32_t)(wql*256 + kc*32);
            uint32_t aaddr = sbase + S_STG + (uint32_t)arow*2048 + ((kb + asel) ^ ax);
            uint32_t ah[4];
            ldm_x4(ah, aaddr);
            uint32_t bkb = (kb + bsel) ^ bx;
            uint32_t baddr = sbase + S_WAHI + (uint32_t)brow7*2048 + bkb;
            uint32_t bh2[2], bl2[2];
            ldm_x2(bh2, baddr);
            ldm_x2(bl2, baddr + 16384);
            mma_bf16(accA, ah, bh2);
            mma_bf16(accA, ah, bl2);
        }
        __syncthreads();
        {
            int bq = l >> 2, cq = (l & 3) * 2;
            stg[(cq*16 + bq)*9 + wql]           = accA[0];
            stg[((cq+1)*16 + bq)*9 + wql]       = accA[1];
            stg[(cq*16 + bq + 8)*9 + wql]       = accA[2];
            stg[((cq+1)*16 + bq + 8)*9 + wql]   = accA[3];
        }
        __syncthreads();
        if (tid < 128) {
            const float* pp = stg + (j0G*16 + bG)*9;
            float s = ((pp[0]+pp[1]) + (pp[2]+pp[3])) + ((pp[4]+pp[5]) + (pp[6]+pp[7]));
            float mval = s * mxv;
            __nv_bfloat16 mh = __float2bfloat16(mval);
            __stcg((short*)&d_mthi[bG*H_ + bk*8 + j0G], *(short*)&mh);
        }
        gbar(tgt); tgt += NBLK;

        {   // stage m (hi only)
            #pragma unroll
            for (int p = 0; p < 8; p++) {
                int j = tid + p * 256;
                int b = j >> 7, c = j & 127;
                uint4 v = __ldcg((const uint4*)d_mthi + j);
                *(uint4*)(smc + S_STG + b*2048 + ((c*16) ^ ((b&7)*16))) = v;
            }
        }
        __syncthreads();

        // phase B (2-pass)
        float acc[4][4];
        #pragma unroll
        for (int nt = 0; nt < 4; nt++)
            #pragma unroll
            for (int u = 0; u < 4; u++) acc[nt][u] = 0.f;
        #pragma unroll
        for (int kc = 0; kc < 8; kc++) {
            uint32_t kb = (uint32_t)(wql*256 + kc*32);
            uint32_t aaddr = sbase + S_STG + (uint32_t)arow*2048 + ((kb + asel) ^ ax);
            uint32_t ah[4];
            ldm_x4(ah, aaddr);
            uint32_t bkb = (kb + bsel) ^ bx;
            #pragma unroll
            for (int nt = 0; nt < 4; nt++) {
                uint32_t baddr = sbase + S_WBHI + (uint32_t)(nt*8 + brow7)*2048 + bkb;
                uint32_t bh[2], bl[2];
                ldm_x2(bh, baddr);
                ldm_x2(bl, baddr + 65536);
                mma_bf16(acc[nt], ah, bh);
                mma_bf16(acc[nt], ah, bl);
            }
        }
        __syncthreads();
        {
            int bq = l >> 2, cq = (l & 3) * 2;
            #pragma unroll
            for (int nt = 0; nt < 4; nt++) {
                int c0 = nt*8 + cq;
                stg[(c0*16 + bq)*9 + wql]          = acc[nt][0];
                stg[((c0+1)*16 + bq)*9 + wql]      = acc[nt][1];
                stg[(c0*16 + bq + 8)*9 + wql]      = acc[nt][2];
                stg[((c0+1)*16 + bq + 8)*9 + wql]  = acc[nt][3];
            }
        }
        __syncthreads();

        {
            const float* p0 = stg + (rci[0]*16 + rb[0])*9;
            float s0 = ((p0[0]+p0[1]) + (p0[2]+p0[3])) + ((p0[4]+p0[5]) + (p0[6]+p0[7]));
            stg[8192 + rb[0]*32 + rci[0]] = zpre0 + s0;
            const float* p1 = stg + (rci[1]*16 + rb[1])*9;
            float s1 = ((p1[0]+p1[1]) + (p1[2]+p1[3])) + ((p1[4]+p1[5]) + (p1[6]+p1[7]));
            stg[8192 + rb[1]*32 + rci[1]] = zpre1 + s1;
        }
        __syncthreads();

        if (tid < 128) {
            float zi = stg[8192 + bG*32 +      j0G];
            float zf = stg[8192 + bG*32 +  8 + j0G];
            float zo = stg[8192 + bG*32 + 16 + j0G];
            float zu = stg[8192 + bG*32 + 24 + j0G];
            float ig = 1.f / (1.f + expf(-zi));
            float fg = 1.f / (1.f + expf(-zf));
            float og = 1.f / (1.f + expf(-zo));
            float ug = tanhf(zu);
            creg = fg * creg + ig * ug;
            float h = og * tanhf(creg);
            int col = bk*8 + j0G;
            __nv_bfloat16 hh = __float2bfloat16(h);
            __stcg((short*)&d_hhi[bG*H_ + col], *(short*)&hh);
            hshi[(size_t)(bG*T_ + t)*H_ + col] = hh;
        }
        gbar(tgt); tgt += NBLK;
    }
}

// ---------------- launcher ----------------
extern "C" void kernel_launch(void* const* d_in, const int* in_sizes, int n_in,
                              void* d_out, int out_size) {
    (void)in_sizes; (void)n_in; (void)out_size;
    const int*   xs      = (const int*)  d_in[0];
    const int*   ys      = (const int*)  d_in[1];
    const float* embed_w = (const float*)d_in[2];
    const float* wx      = (const float*)d_in[3];
    const float* wh      = (const float*)d_in[4];
    const float* wmx     = (const float*)d_in[5];
    const float* wmh     = (const float*)d_in[6];
    const float* bb      = (const float*)d_in[7];
    const float* gx      = (const float*)d_in[8];
    const float* gh      = (const float*)d_in[9];
    const float* gmx     = (const float*)d_in[10];
    const float* gmh     = (const float*)d_in[11];
    const float* pred_w  = (const float*)d_in[12];
    const float* pred_b  = (const float*)d_in[13];
    float* out = (float*)d_out;

    float *p_whnT, *p_wmhnT, *p_zx, *p_mx, *p_rownll;
    float *p_nwx, *p_nwh, *p_nwmx, *p_nwmh;
    __nv_bfloat16 *p_xhi, *p_xlo, *p_wxnThi, *p_wxnTlo, *p_wmxnThi, *p_wmxnTlo;
    __nv_bfloat16 *p_pwhi, *p_hshi;
    cudaGetSymbolAddress((void**)&p_whnT,    d_whnT);
    cudaGetSymbolAddress((void**)&p_wmhnT,   d_wmhnT);
    cudaGetSymbolAddress((void**)&p_zx,      d_zx);
    cudaGetSymbolAddress((void**)&p_mx,      d_mx);
    cudaGetSymbolAddress((void**)&p_rownll,  d_rownll);
    cudaGetSymbolAddress((void**)&p_nwx,     d_nwx);
    cudaGetSymbolAddress((void**)&p_nwh,     d_nwh);
    cudaGetSymbolAddress((void**)&p_nwmx,    d_nwmx);
    cudaGetSymbolAddress((void**)&p_nwmh,    d_nwmh);
    cudaGetSymbolAddress((void**)&p_xhi,     d_xhi);
    cudaGetSymbolAddress((void**)&p_xlo,     d_xlo);
    cudaGetSymbolAddress((void**)&p_wxnThi,  d_wxnThi);
    cudaGetSymbolAddress((void**)&p_wxnTlo,  d_wxnTlo);
    cudaGetSymbolAddress((void**)&p_wmxnThi, d_wmxnThi);
    cudaGetSymbolAddress((void**)&p_wmxnTlo, d_wmxnTlo);
    cudaGetSymbolAddress((void**)&p_pwhi,    d_pwhi);
    cudaGetSymbolAddress((void**)&p_hshi,    d_hshi);

    static bool attr_set = false;
    if (!attr_set) {
        cudaFuncSetAttribute(recur_kernel, cudaFuncAttributeMaxDynamicSharedMemorySize, RS_BYTES);
        cudaFuncSetAttribute(mma_gemm<true, false>, cudaFuncAttributeMaxDynamicSharedMemorySize, GSMEM);
        cudaFuncSetAttribute(mma_gemm<false, true>, cudaFuncAttributeMaxDynamicSharedMemorySize, GSMEM);
        cudaFuncSetAttribute(logits_nll_kernel, cudaFuncAttributeMaxDynamicSharedMemorySize, GSMEM);
        attr_set = true;
    }

    // weight norm
    zero_norms_kernel<<<16, 256>>>();
    sumsq4_kernel<<<dim3(16, 4, 32), 256>>>(wx, wh, wmx, wmh);
    scaleT_bf16_kernel<<<dim3(FH/32, E_/32), dim3(32,8)>>>(wx,  gx,  p_nwx,  p_wxnThi,  p_wxnTlo,  E_, FH);
    scaleT_bf16_kernel<<<dim3(H_/32, E_/32), dim3(32,8)>>>(wmx, gmx, p_nwmx, p_wmxnThi, p_wmxnTlo, E_, H_);
    scaleT_kernel<<<dim3(FH/32, H_/32), dim3(32,8)>>>(wh,  gh,  p_nwh,  p_whnT,  H_, FH);
    scaleT_kernel<<<dim3(H_/32, H_/32), dim3(32,8)>>>(wmh, gmh, p_nwmh, p_wmhnT, H_, H_);
    split_hi_kernel<<<(int)(((size_t)V_*H_ + 255)/256), 256>>>(pred_w, p_pwhi, (size_t)V_*H_);

    // embedding
    embed_kernel<<<B_*T_, 128>>>(xs, embed_w, p_xhi, p_xlo);

    // input projections: zx 2-pass, mx 3-pass
    mma_gemm<true,  false><<<dim3(FH/128, (B_*T_)/128), 256, GSMEM>>>(
        p_xhi, p_xlo, p_wxnThi, p_wxnTlo, bb, p_zx, B_*T_, FH, E_);
    mma_gemm<false, true ><<<dim3(H_/128, (B_*T_)/128), 256, GSMEM>>>(
        p_xhi, p_xlo, p_wmxnThi, p_wmxnTlo, (const float*)nullptr, p_mx, B_*T_, H_, E_);

    // recurrence (hi-only state staging, 2-pass phases)
    reset_bar_kernel<<<1, 1>>>();
    recur_kernel<<<NBLK, 256, RS_BYTES>>>(
        p_zx, p_mx, p_wmhnT, p_whnT, p_hshi);

    // fused logits (1-pass bf16) + softmax partials + loss
    logits_nll_kernel<<<dim3(NCB, (B_*T_)/128), 256, GSMEM>>>(
        p_hshi, p_pwhi, pred_b, ys);
    nll_reduce_kernel<<<(B_*T_)/256, 256>>>(p_rownll);
    mean_kernel<<<1, 256>>>(p_rownll, out);
}

// round 16
// speedup vs baseline: 1.5335x; 1.0727x over previous
#include <cuda_runtime.h>
#include <cuda_bf16.h>
#include <cstdint>

#define B_  16
#define T_  512
#define V_  8192
#define E_  512
#define H_  1024
#define FH  4096
#define NBLK 128
#define NCB (V_/128)        // 64 column-blocks for logits

// ---------------- device scratch ----------------
__device__ __nv_bfloat16 d_xhi[B_*T_*E_], d_xlo[B_*T_*E_];
__device__ __nv_bfloat16 d_wxnThi[(size_t)FH*E_], d_wxnTlo[(size_t)FH*E_];
__device__ __nv_bfloat16 d_wmxnThi[H_*E_], d_wmxnTlo[H_*E_];
__device__ __nv_bfloat16 d_pwhi[(size_t)V_*H_];
__device__ __nv_bfloat16 d_hshi[B_*T_*H_];
__device__ float d_whnT[(size_t)FH*H_];
__device__ float d_wmhnT[H_*H_];
__device__ float d_nwx[FH], d_nwh[FH], d_nwmx[H_], d_nwmh[H_];
__device__ float d_zx[(size_t)B_*T_*FH];
__device__ float d_mx[B_*T_*H_];
__device__ __nv_bfloat16 d_hhi[B_*H_];
__device__ __nv_bfloat16 d_mthi[B_*H_];
__device__ float d_pmax[(size_t)B_*T_*NCB];
__device__ float d_psum[(size_t)B_*T_*NCB];
__device__ float d_tlogit[B_*T_];
__device__ float d_rownll[B_*T_];
__device__ unsigned g_barcnt;

// ---------------- helpers ----------------
__device__ __forceinline__ uint32_t smem_u32(const void* p) {
    uint32_t a;
    asm("{ .reg .u64 t; cvta.to.shared.u64 t, %1; cvt.u32.u64 %0, t; }" : "=r"(a) : "l"(p));
    return a;
}
__device__ __forceinline__ void ldm_x4(uint32_t* r, uint32_t addr) {
    asm volatile("ldmatrix.sync.aligned.m8n8.x4.shared.b16 {%0,%1,%2,%3}, [%4];"
                 : "=r"(r[0]), "=r"(r[1]), "=r"(r[2]), "=r"(r[3]) : "r"(addr));
}
__device__ __forceinline__ void ldm_x2(uint32_t* r, uint32_t addr) {
    asm volatile("ldmatrix.sync.aligned.m8n8.x2.shared.b16 {%0,%1}, [%2];"
                 : "=r"(r[0]), "=r"(r[1]) : "r"(addr));
}
__device__ __forceinline__ void mma_bf16(float* c, const uint32_t* a, const uint32_t* b) {
    asm volatile("mma.sync.aligned.m16n8k16.row.col.f32.bf16.bf16.f32 "
                 "{%0,%1,%2,%3}, {%4,%5,%6,%7}, {%8,%9}, {%0,%1,%2,%3};"
                 : "+f"(c[0]), "+f"(c[1]), "+f"(c[2]), "+f"(c[3])
                 : "r"(a[0]), "r"(a[1]), "r"(a[2]), "r"(a[3]), "r"(b[0]), "r"(b[1]));
}
__device__ __forceinline__ uint32_t pk(__nv_bfloat16 a, __nv_bfloat16 b) {
    __nv_bfloat162 t = __halves2bfloat162(a, b);
    return *(uint32_t*)&t;
}
__device__ __forceinline__ void cpa16(uint32_t saddr, const void* g) {
    asm volatile("cp.async.cg.shared.global [%0], [%1], 16;" :: "r"(saddr), "l"(g) : "memory");
}

// ---------------- weight norm ----------------
__global__ void zero_norms_kernel() {
    int i = blockIdx.x * 256 + threadIdx.x;
    if (i < FH) { d_nwx[i] = 0.f; d_nwh[i] = 0.f; }
    if (i < H_) { d_nwmx[i] = 0.f; d_nwmh[i] = 0.f; }
}
__global__ void sumsq4_kernel(const float* __restrict__ wx, const float* __restrict__ wh,
                              const float* __restrict__ wmx, const float* __restrict__ wmh) {
    int id = blockIdx.y;
    const float* w; float* nrm; int K, N;
    if (id == 0)      { w = wx;  nrm = d_nwx;  K = E_; N = FH; }
    else if (id == 1) { w = wh;  nrm = d_nwh;  K = H_; N = FH; }
    else if (id == 2) { w = wmx; nrm = d_nwmx; K = E_; N = H_; }
    else              { w = wmh; nrm = d_nwmh; K = H_; N = H_; }
    int j = blockIdx.x * 256 + threadIdx.x;
    int k0 = blockIdx.z * 32;
    if (j >= N || k0 >= K) return;
    float ss = 0.f;
    #pragma unroll 4
    for (int k = k0; k < k0 + 32; k++) { float v = w[(size_t)k*N + j]; ss += v*v; }
    atomicAdd(&nrm[j], ss);
}
__global__ void scaleT_kernel(const float* __restrict__ w, const float* __restrict__ g,
                              const float* __restrict__ nrm, float* __restrict__ out,
                              int K, int N) {
    __shared__ float tile[32][33];
    int n0 = blockIdx.x * 32, k0 = blockIdx.y * 32;
    int tx = threadIdx.x, ty = threadIdx.y;
    for (int r = ty; r < 32; r += 8)
        tile[r][tx] = w[(size_t)(k0 + r)*N + n0 + tx];
    __syncthreads();
    for (int r = ty; r < 32; r += 8) {
        int n = n0 + r;
        float s = g[n] / fmaxf(sqrtf(nrm[n]), 1e-12f);
        out[(size_t)n*K + k0 + tx] = tile[tx][r] * s;
    }
}
__global__ void scaleT_bf16_kernel(const float* __restrict__ w, const float* __restrict__ g,
                                   const float* __restrict__ nrm,
                                   __nv_bfloat16* __restrict__ ohi,
                                   __nv_bfloat16* __restrict__ olo,
                                   int K, int N) {
    __shared__ float tile[32][33];
    int n0 = blockIdx.x * 32, k0 = blockIdx.y * 32;
    int tx = threadIdx.x, ty = threadIdx.y;
    for (int r = ty; r < 32; r += 8)
        tile[r][tx] = w[(size_t)(k0 + r)*N + n0 + tx];
    __syncthreads();
    for (int r = ty; r < 32; r += 8) {
        int n = n0 + r;
        float s = g[n] / fmaxf(sqrtf(nrm[n]), 1e-12f);
        float v = tile[tx][r] * s;
        __nv_bfloat16 hi = __float2bfloat16(v);
        ohi[(size_t)n*K + k0 + tx] = hi;
        olo[(size_t)n*K + k0 + tx] = __float2bfloat16(v - __bfloat162float(hi));
    }
}
__global__ void split_hi_kernel(const float* __restrict__ w,
                                __nv_bfloat16* __restrict__ ohi, size_t total) {
    size_t i = (size_t)blockIdx.x * 256 + threadIdx.x;
    if (i >= total) return;
    ohi[i] = __float2bfloat16(w[i]);
}

// ---------------- embedding ----------------
__global__ void embed_kernel(const int* __restrict__ xs, const float* __restrict__ ew,
                             __nv_bfloat16* __restrict__ xhi, __nv_bfloat16* __restrict__ xlo) {
    int r = blockIdx.x;
    int idx = xs[r];
    const float4* src = (const float4*)(ew + (size_t)idx * E_);
    float4 v = src[threadIdx.x];
    if (idx == 0) v = make_float4(0.f, 0.f, 0.f, 0.f);
    size_t base = (size_t)r * E_ + threadIdx.x * 4;
    float vv[4] = {v.x, v.y, v.z, v.w};
    #pragma unroll
    for (int u = 0; u < 4; u++) {
        __nv_bfloat16 hi = __float2bfloat16(vv[u]);
        xhi[base + u] = hi;
        xlo[base + u] = __float2bfloat16(vv[u] - __bfloat162float(hi));
    }
}

// ---------------- mma.sync split-bf16 GEMM cores ----------------
#define GSMEM 131072

template<bool THIRD>
__device__ __forceinline__ void gemm_main3(
    char* smem, uint32_t sbase,
    const __nv_bfloat16* Ahi, const __nv_bfloat16* Alo,
    const __nv_bfloat16* Bhi, const __nv_bfloat16* Blo,
    int bm, int bn, int K, float acc[4][4][4])
{
    const int tid = threadIdx.x, lid = tid & 31, wid = tid >> 5;
    const int wm = (wid & 1) * 64, wn = (wid >> 1) * 32;
    #pragma unroll
    for (int mt = 0; mt < 4; mt++)
        #pragma unroll
        for (int nt = 0; nt < 4; nt++)
            #pragma unroll
            for (int u = 0; u < 4; u++) acc[mt][nt][u] = 0.f;

    auto issue = [&](int ch, int buf) {
        int k0 = ch << 6;
        #pragma unroll
        for (int p = 0; p < 16; p++) {
            int i = tid + p * 256;
            int tile = i >> 10, j = i & 1023;
            int row = j >> 3, c = j & 7;
            const __nv_bfloat16* src = (tile == 0) ? Ahi : (tile == 1) ? Alo
                                     : (tile == 2) ? Bhi : Blo;
            int grow = ((tile < 2) ? bm : bn) + row;
            uint32_t sa = sbase + (uint32_t)buf*65536 + tile*16384
                        + (row * 8 + (c ^ (row & 7))) * 16;
            cpa16(sa, src + (size_t)grow * K + k0 + c * 8);
        }
        asm volatile("cp.async.commit_group;" ::: "memory");
    };

    const int nchunk = K >> 6;
    issue(0, 0);
    for (int ch = 0; ch < nchunk; ch++) {
        if (ch + 1 < nchunk) {
            issue(ch + 1, (ch + 1) & 1);
            asm volatile("cp.async.wait_group 1;" ::: "memory");
        } else {
            asm volatile("cp.async.wait_group 0;" ::: "memory");
        }
        __syncthreads();
        const uint32_t boff = sbase + (uint32_t)((ch & 1) * 65536);
        #pragma unroll
        for (int ks = 0; ks < 4; ks++) {
            uint32_t bh[4][2], bl[4][2];
            {
                int row = wn + (lid & 7);
                int cc = 2 * ks + ((lid >> 3) & 1);
                #pragma unroll
                for (int nt = 0; nt < 4; nt++) {
                    int r = row + nt * 8;
                    uint32_t addr = boff + 32768 + (r * 8 + (cc ^ (r & 7))) * 16;
                    ldm_x2(bh[nt], addr);
                    ldm_x2(bl[nt], addr + 16384);
                }
            }
            #pragma unroll
            for (int mt = 0; mt < 4; mt++) {
                int r = wm + mt * 16 + (lid & 7) + ((lid >> 3) & 1) * 8;
                int cc = 2 * ks + (lid >> 4);
                uint32_t addr = boff + (r * 8 + (cc ^ (r & 7))) * 16;
                uint32_t ah[4], al[4];
                ldm_x4(ah, addr);
                ldm_x4(al, addr + 16384);
                #pragma unroll
                for (int nt = 0; nt < 4; nt++) {
                    mma_bf16(acc[mt][nt], ah, bh[nt]);
                    mma_bf16(acc[mt][nt], ah, bl[nt]);
                    if (THIRD) mma_bf16(acc[mt][nt], al, bh[nt]);
                }
            }
        }
        __syncthreads();
    }
}

__device__ __forceinline__ void gemm_main1(
    char* smem, uint32_t sbase,
    const __nv_bfloat16* Ahi, const __nv_bfloat16* Bhi,
    int bm, int bn, int K, float acc[4][4][4])
{
    const int tid = threadIdx.x, lid = tid & 31, wid = tid >> 5;
    const int wm = (wid & 1) * 64, wn = (wid >> 1) * 32;
    #pragma unroll
    for (int mt = 0; mt < 4; mt++)
        #pragma unroll
        for (int nt = 0; nt < 4; nt++)
            #pragma unroll
            for (int u = 0; u < 4; u++) acc[mt][nt][u] = 0.f;

    auto issue = [&](int ch, int buf) {
        int k0 = ch << 6;
        #pragma unroll
        for (int p = 0; p < 8; p++) {
            int i = tid + p * 256;
            int tile = i >> 10, j = i & 1023;
            int row = j >> 3, c = j & 7;
            const __nv_bfloat16* src = (tile == 0) ? Ahi : Bhi;
            int grow = ((tile == 0) ? bm : bn) + row;
            uint32_t sa = sbase + (uint32_t)buf*32768 + tile*16384
                        + (row * 8 + (c ^ (row & 7))) * 16;
            cpa16(sa, src + (size_t)grow * K + k0 + c * 8);
        }
        asm volatile("cp.async.commit_group;" ::: "memory");
    };

    const int nchunk = K >> 6;
    issue(0, 0);
    for (int ch = 0; ch < nchunk; ch++) {
        if (ch + 1 < nchunk) {
            issue(ch + 1, (ch + 1) & 1);
            asm volatile("cp.async.wait_group 1;" ::: "memory");
        } else {
            asm volatile("cp.async.wait_group 0;" ::: "memory");
        }
        __syncthreads();
        const uint32_t boff = sbase + (uint32_t)((ch & 1) * 32768);
        #pragma unroll
        for (int ks = 0; ks < 4; ks++) {
            uint32_t bh[4][2];
            {
                int row = wn + (lid & 7);
                int cc = 2 * ks + ((lid >> 3) & 1);
                #pragma unroll
                for (int nt = 0; nt < 4; nt++) {
                    int r = row + nt * 8;
                    ldm_x2(bh[nt], boff + 16384 + (r * 8 + (cc ^ (r & 7))) * 16);
                }
            }
            #pragma unroll
            for (int mt = 0; mt < 4; mt++) {
                int r = wm + mt * 16 + (lid & 7) + ((lid >> 3) & 1) * 8;
                int cc = 2 * ks + (lid >> 4);
                uint32_t ah[4];
                ldm_x4(ah, boff + (r * 8 + (cc ^ (r & 7))) * 16);
                #pragma unroll
                for (int nt = 0; nt < 4; nt++)
                    mma_bf16(acc[mt][nt], ah, bh[nt]);
            }
        }
        __syncthreads();
    }
}

template<bool BIAS, bool THIRD>
__global__ void __launch_bounds__(256) mma_gemm(
    const __nv_bfloat16* __restrict__ Ahi, const __nv_bfloat16* __restrict__ Alo,
    const __nv_bfloat16* __restrict__ Bhi, const __nv_bfloat16* __restrict__ Blo,
    const float* __restrict__ bias, float* __restrict__ C,
    int M, int N, int K)
{
    extern __shared__ char smem[];
    const uint32_t sbase = smem_u32(smem);
    const int tid = threadIdx.x, lid = tid & 31, wid = tid >> 5;
    const int wm = (wid & 1) * 64, wn = (wid >> 1) * 32;
    const int bn = blockIdx.x * 128, bm = blockIdx.y * 128;
    float acc[4][4][4];
    gemm_main3<THIRD>(smem, sbase, Ahi, Alo, Bhi, Blo, bm, bn, K, acc);

    const int mrow = (lid >> 2), ncol = (lid & 3) * 2;
    #pragma unroll
    for (int mt = 0; mt < 4; mt++) {
        #pragma unroll
        for (int nt = 0; nt < 4; nt++) {
            int row0 = bm + wm + mt * 16 + mrow;
            int col = bn + wn + nt * 8 + ncol;
            float2 v0 = make_float2(acc[mt][nt][0], acc[mt][nt][1]);
            float2 v1 = make_float2(acc[mt][nt][2], acc[mt][nt][3]);
            if (BIAS) {
                float b0 = bias[col], b1 = bias[col + 1];
                v0.x += b0; v0.y += b1;
                v1.x += b0; v1.y += b1;
            }
            *(float2*)&C[(size_t)row0 * N + col] = v0;
            *(float2*)&C[(size_t)(row0 + 8) * N + col] = v1;
        }
    }
}

// ---------------- fused logits (1-pass bf16) + online-softmax partials ----------------
__global__ void __launch_bounds__(256) logits_nll_kernel(
    const __nv_bfloat16* __restrict__ Ahi,
    const __nv_bfloat16* __restrict__ Bhi,
    const float* __restrict__ bias, const int* __restrict__ ys)
{
    extern __shared__ char smem[];
    const uint32_t sbase = smem_u32(smem);
    const int tid = threadIdx.x, lid = tid & 31, wid = tid >> 5;
    const int wm = (wid & 1) * 64, wn = (wid >> 1) * 32;
    const int bn = blockIdx.x * 128, bm = blockIdx.y * 128;
    float acc[4][4][4];
    gemm_main1(smem, sbase, Ahi, Bhi, bm, bn, H_, acc);

    float* smc = (float*)smem;
    const int mrow = (lid >> 2), ncol = (lid & 3) * 2;
    #pragma unroll
    for (int mt = 0; mt < 4; mt++) {
        #pragma unroll
        for (int nt = 0; nt < 4; nt++) {
            int r = wm + mt * 16 + mrow;
            int c = wn + nt * 8 + ncol;
            float b0 = bias[bn + c], b1 = bias[bn + c + 1];
            smc[r * 132 + c]             = acc[mt][nt][0] + b0;
            smc[r * 132 + c + 1]         = acc[mt][nt][1] + b1;
            smc[(r + 8) * 132 + c]       = acc[mt][nt][2] + b0;
            smc[(r + 8) * 132 + c + 1]   = acc[mt][nt][3] + b1;
        }
    }
    __syncthreads();

    int row = tid >> 1, half = tid & 1;
    const float* lr = smc + row * 132 + half * 64;
    float m = -3.4e38f, s = 0.f;
    #pragma unroll 8
    for (int c = 0; c < 64; c++) {
        float x = lr[c];
        float nm = fmaxf(m, x);
        s = s * __expf(m - nm) + __expf(x - nm);
        m = nm;
    }
    float m2 = __shfl_xor_sync(0xFFFFFFFF, m, 1);
    float s2 = __shfl_xor_sync(0xFFFFFFFF, s, 1);
    float M = fmaxf(m, m2);
    float S = s * __expf(m - M) + s2 * __expf(m2 - M);
    int grow = bm + row;
    if (half == 0) {
        d_pmax[(size_t)grow * NCB + blockIdx.x] = M;
        d_psum[(size_t)grow * NCB + blockIdx.x] = S;
        int target = ys[grow];
        if (target >= bn && target < bn + 128)
            d_tlogit[grow] = smc[row * 132 + (target - bn)];
    }
}

__global__ void nll_reduce_kernel(float* __restrict__ rownll) {
    int row = blockIdx.x * 256 + threadIdx.x;
    const float* pm = d_pmax + (size_t)row * NCB;
    const float* ps = d_psum + (size_t)row * NCB;
    float m = -3.4e38f, s = 0.f;
    #pragma unroll 8
    for (int c = 0; c < NCB; c++) {
        float m2 = pm[c], s2 = ps[c];
        float M = fmaxf(m, m2);
        s = s * __expf(m - M) + s2 * __expf(m2 - M);
        m = M;
    }
    rownll[row] = -(d_tlogit[row] - m - logf(s));
}

__global__ void mean_kernel(const float* __restrict__ rownll, float* __restrict__ out) {
    __shared__ float sred[256];
    int tid = threadIdx.x;
    float s = 0.f;
    for (int i = tid; i < B_*T_; i += 256) s += rownll[i];
    sred[tid] = s; __syncthreads();
    for (int k = 128; k > 0; k >>= 1) {
        if (tid < k) sred[tid] += sred[tid + k];
        __syncthreads();
    }
    if (tid == 0) out[0] = sred[0] / (float)(B_*T_);
}

// ---------------- persistent recurrence: hi-only state + hi-only weights (1-pass) ----------------
__global__ void reset_bar_kernel() { g_barcnt = 0u; }

__device__ __forceinline__ void gbar(unsigned target) {
    __syncthreads();
    if (threadIdx.x == 0) {
        asm volatile("red.release.gpu.global.add.u32 [%0], %1;"
                     :: "l"(&g_barcnt), "r"(1u) : "memory");
        unsigned v;
        do {
            asm volatile("ld.acquire.gpu.global.u32 %0, [%1];"
                         : "=r"(v) : "l"(&g_barcnt) : "memory");
        } while (v < target);
    }
    __syncthreads();
}

// smem: wBhi 64KB | wAhi 16KB | stage/overlay 40KB
#define S_WBHI  0
#define S_WAHI  65536
#define S_STG   81920
#define RS_BYTES 122880

__global__ void __launch_bounds__(256) recur_kernel(
    const float* __restrict__ zx, const float* __restrict__ mxp,
    const float* __restrict__ wmhnT, const float* __restrict__ whnT,
    __nv_bfloat16* __restrict__ hshi)
{
    extern __shared__ char smc[];
    float* stg = (float*)(smc + S_STG);
    const uint32_t sbase = smem_u32(smc);
    const int bk = blockIdx.x, tid = threadIdx.x;

    // one-time weight preload (hi only, ldmatrix-swizzled rows)
    #pragma unroll 4
    for (int p = 0; p < 32; p++) {
        int col = (p >> 3) * H_ + bk * 8 + (p & 7);
        float4 v = ((const float4*)(whnT + (size_t)col * H_))[tid];
        uint32_t off = p * 2048 + ((tid * 8) ^ ((p & 7) * 16));
        *(uint2*)(smc + S_WBHI + off) = make_uint2(
            pk(__float2bfloat16(v.x), __float2bfloat16(v.y)),
            pk(__float2bfloat16(v.z), __float2bfloat16(v.w)));
    }
    #pragma unroll
    for (int p = 0; p < 8; p++) {
        int col = bk * 8 + p;
        float4 v = ((const float4*)(wmhnT + (size_t)col * H_))[tid];
        uint32_t off = p * 2048 + ((tid * 8) ^ (p * 16));
        *(uint2*)(smc + S_WAHI + off) = make_uint2(
            pk(__float2bfloat16(v.x), __float2bfloat16(v.y)),
            pk(__float2bfloat16(v.z), __float2bfloat16(v.w)));
    }
    if (tid < 128) {
        int b = tid >> 3, col = bk*8 + (tid & 7);
        ((short*)d_hhi)[b*H_ + col] = 0;
    }
    unsigned tgt = NBLK;
    gbar(tgt); tgt += NBLK;

    const int l = tid & 31, wql = tid >> 5;
    const int arow = (l & 7) + ((l >> 3) & 1) * 8;
    const uint32_t ax = (uint32_t)((arow & 7) * 16);
    const uint32_t asel = ((uint32_t)(l >> 4)) << 4;
    const int brow7 = l & 7;
    const uint32_t bx = (uint32_t)(brow7 * 16);
    const uint32_t bsel = ((uint32_t)((l >> 3) & 1)) << 4;
    int rci[2], rb[2]; size_t rzoff[2];
    #pragma unroll
    for (int o = 0; o < 2; o++) {
        int out = tid + o*256;
        rci[o] = out >> 4; rb[o] = out & 15;
        int q = rci[o] >> 3, j0 = rci[o] & 7;
        rzoff[o] = (size_t)rb[o]*T_*FH + (size_t)q*H_ + bk*8 + j0;
    }
    const int bG = tid >> 3, j0G = tid & 7;
    float creg = 0.f;

    for (int t = 0; t < T_; t++) {
        float zpre0 = __ldg(&zx[rzoff[0] + (size_t)t*FH]);
        float zpre1 = __ldg(&zx[rzoff[1] + (size_t)t*FH]);
        float mxv = 0.f;
        if (tid < 128) mxv = __ldg(&mxp[(size_t)(bG*T_ + t)*H_ + bk*8 + j0G]);

        {   // stage h (hi only: 32KB)
            #pragma unroll
            for (int p = 0; p < 8; p++) {
                int j = tid + p * 256;
                int b = j >> 7, c = j & 127;
                uint4 v = __ldcg((const uint4*)d_hhi + j);
                *(uint4*)(smc + S_STG + b*2048 + ((c*16) ^ ((b&7)*16))) = v;
            }
        }
        __syncthreads();

        // phase A (1-pass)
        float accA[4] = {0.f, 0.f, 0.f, 0.f};
        #pragma unroll
        for (int kc = 0; kc < 8; kc++) {
            uint32_t kb = (uint32_t)(wql*256 + kc*32);
            uint32_t aaddr = sbase + S_STG + (uint32_t)arow*2048 + ((kb + asel) ^ ax);
            uint32_t ah[4];
            ldm_x4(ah, aaddr);
            uint32_t bkb = (kb + bsel) ^ bx;
            uint32_t bh2[2];
            ldm_x2(bh2, sbase + S_WAHI + (uint32_t)brow7*2048 + bkb);
            mma_bf16(accA, ah, bh2);
        }
        __syncthreads();
        {
            int bq = l >> 2, cq = (l & 3) * 2;
            stg[(cq*16 + bq)*9 + wql]           = accA[0];
            stg[((cq+1)*16 + bq)*9 + wql]       = accA[1];
            stg[(cq*16 + bq + 8)*9 + wql]       = accA[2];
            stg[((cq+1)*16 + bq + 8)*9 + wql]   = accA[3];
        }
        __syncthreads();
        if (tid < 128) {
            const float* pp = stg + (j0G*16 + bG)*9;
            float s = ((pp[0]+pp[1]) + (pp[2]+pp[3])) + ((pp[4]+pp[5]) + (pp[6]+pp[7]));
            float mval = s * mxv;
            __nv_bfloat16 mh = __float2bfloat16(mval);
            __stcg((short*)&d_mthi[bG*H_ + bk*8 + j0G], *(short*)&mh);
        }
        gbar(tgt); tgt += NBLK;

        {   // stage m (hi only)
            #pragma unroll
            for (int p = 0; p < 8; p++) {
                int j = tid + p * 256;
                int b = j >> 7, c = j & 127;
                uint4 v = __ldcg((const uint4*)d_mthi + j);
                *(uint4*)(smc + S_STG + b*2048 + ((c*16) ^ ((b&7)*16))) = v;
            }
        }
        __syncthreads();

        // phase B (1-pass)
        float acc[4][4];
        #pragma unroll
        for (int nt = 0; nt < 4; nt++)
            #pragma unroll
            for (int u = 0; u < 4; u++) acc[nt][u] = 0.f;
        #pragma unroll
        for (int kc = 0; kc < 8; kc++) {
            uint32_t kb = (uint32_t)(wql*256 + kc*32);
            uint32_t aaddr = sbase + S_STG + (uint32_t)arow*2048 + ((kb + asel) ^ ax);
            uint32_t ah[4];
            ldm_x4(ah, aaddr);
            uint32_t bkb = (kb + bsel) ^ bx;
            #pragma unroll
            for (int nt = 0; nt < 4; nt++) {
                uint32_t bh[2];
                ldm_x2(bh, sbase + S_WBHI + (uint32_t)(nt*8 + brow7)*2048 + bkb);
                mma_bf16(acc[nt], ah, bh);
            }
        }
        __syncthreads();
        {
            int bq = l >> 2, cq = (l & 3) * 2;
            #pragma unroll
            for (int nt = 0; nt < 4; nt++) {
                int c0 = nt*8 + cq;
                stg[(c0*16 + bq)*9 + wql]          = acc[nt][0];
                stg[((c0+1)*16 + bq)*9 + wql]      = acc[nt][1];
                stg[(c0*16 + bq + 8)*9 + wql]      = acc[nt][2];
                stg[((c0+1)*16 + bq + 8)*9 + wql]  = acc[nt][3];
            }
        }
        __syncthreads();

        {
            const float* p0 = stg + (rci[0]*16 + rb[0])*9;
            float s0 = ((p0[0]+p0[1]) + (p0[2]+p0[3])) + ((p0[4]+p0[5]) + (p0[6]+p0[7]));
            stg[8192 + rb[0]*32 + rci[0]] = zpre0 + s0;
            const float* p1 = stg + (rci[1]*16 + rb[1])*9;
            float s1 = ((p1[0]+p1[1]) + (p1[2]+p1[3])) + ((p1[4]+p1[5]) + (p1[6]+p1[7]));
            stg[8192 + rb[1]*32 + rci[1]] = zpre1 + s1;
        }
        __syncthreads();

        if (tid < 128) {
            float zi = stg[8192 + bG*32 +      j0G];
            float zf = stg[8192 + bG*32 +  8 + j0G];
            float zo = stg[8192 + bG*32 + 16 + j0G];
            float zu = stg[8192 + bG*32 + 24 + j0G];
            float ig = 1.f / (1.f + expf(-zi));
            float fg = 1.f / (1.f + expf(-zf));
            float og = 1.f / (1.f + expf(-zo));
            float ug = tanhf(zu);
            creg = fg * creg + ig * ug;
            float h = og * tanhf(creg);
            int col = bk*8 + j0G;
            __nv_bfloat16 hh = __float2bfloat16(h);
            __stcg((short*)&d_hhi[bG*H_ + col], *(short*)&hh);
            hshi[(size_t)(bG*T_ + t)*H_ + col] = hh;
        }
        gbar(tgt); tgt += NBLK;
    }
}

// ---------------- launcher ----------------
extern "C" void kernel_launch(void* const* d_in, const int* in_sizes, int n_in,
                              void* d_out, int out_size) {
    (void)in_sizes; (void)n_in; (void)out_size;
    const int*   xs      = (const int*)  d_in[0];
    const int*   ys      = (const int*)  d_in[1];
    const float* embed_w = (const float*)d_in[2];
    const float* wx      = (const float*)d_in[3];
    const float* wh      = (const float*)d_in[4];
    const float* wmx     = (const float*)d_in[5];
    const float* wmh     = (const float*)d_in[6];
    const float* bb      = (const float*)d_in[7];
    const float* gx      = (const float*)d_in[8];
    const float* gh      = (const float*)d_in[9];
    const float* gmx     = (const float*)d_in[10];
    const float* gmh     = (const float*)d_in[11];
    const float* pred_w  = (const float*)d_in[12];
    const float* pred_b  = (const float*)d_in[13];
    float* out = (float*)d_out;

    float *p_whnT, *p_wmhnT, *p_zx, *p_mx, *p_rownll;
    float *p_nwx, *p_nwh, *p_nwmx, *p_nwmh;
    __nv_bfloat16 *p_xhi, *p_xlo, *p_wxnThi, *p_wxnTlo, *p_wmxnThi, *p_wmxnTlo;
    __nv_bfloat16 *p_pwhi, *p_hshi;
    cudaGetSymbolAddress((void**)&p_whnT,    d_whnT);
    cudaGetSymbolAddress((void**)&p_wmhnT,   d_wmhnT);
    cudaGetSymbolAddress((void**)&p_zx,      d_zx);
    cudaGetSymbolAddress((void**)&p_mx,      d_mx);
    cudaGetSymbolAddress((void**)&p_rownll,  d_rownll);
    cudaGetSymbolAddress((void**)&p_nwx,     d_nwx);
    cudaGetSymbolAddress((void**)&p_nwh,     d_nwh);
    cudaGetSymbolAddress((void**)&p_nwmx,    d_nwmx);
    cudaGetSymbolAddress((void**)&p_nwmh,    d_nwmh);
    cudaGetSymbolAddress((void**)&p_xhi,     d_xhi);
    cudaGetSymbolAddress((void**)&p_xlo,     d_xlo);
    cudaGetSymbolAddress((void**)&p_wxnThi,  d_wxnThi);
    cudaGetSymbolAddress((void**)&p_wxnTlo,  d_wxnTlo);
    cudaGetSymbolAddress((void**)&p_wmxnThi, d_wmxnThi);
    cudaGetSymbolAddress((void**)&p_wmxnTlo, d_wmxnTlo);
    cudaGetSymbolAddress((void**)&p_pwhi,    d_pwhi);
    cudaGetSymbolAddress((void**)&p_hshi,    d_hshi);

    static bool attr_set = false;
    if (!attr_set) {
        cudaFuncSetAttribute(recur_kernel, cudaFuncAttributeMaxDynamicSharedMemorySize, RS_BYTES);
        cudaFuncSetAttribute(mma_gemm<true, false>, cudaFuncAttributeMaxDynamicSharedMemorySize, GSMEM);
        cudaFuncSetAttribute(mma_gemm<false, true>, cudaFuncAttributeMaxDynamicSharedMemorySize, GSMEM);
        cudaFuncSetAttribute(logits_nll_kernel, cudaFuncAttributeMaxDynamicSharedMemorySize, GSMEM);
        attr_set = true;
    }

    // weight norm
    zero_norms_kernel<<<16, 256>>>();
    sumsq4_kernel<<<dim3(16, 4, 32), 256>>>(wx, wh, wmx, wmh);
    scaleT_bf16_kernel<<<dim3(FH/32, E_/32), dim3(32,8)>>>(wx,  gx,  p_nwx,  p_wxnThi,  p_wxnTlo,  E_, FH);
    scaleT_bf16_kernel<<<dim3(H_/32, E_/32), dim3(32,8)>>>(wmx, gmx, p_nwmx, p_wmxnThi, p_wmxnTlo, E_, H_);
    scaleT_kernel<<<dim3(FH/32, H_/32), dim3(32,8)>>>(wh,  gh,  p_nwh,  p_whnT,  H_, FH);
    scaleT_kernel<<<dim3(H_/32, H_/32), dim3(32,8)>>>(wmh, gmh, p_nwmh, p_wmhnT, H_, H_);
    split_hi_kernel<<<(int)(((size_t)V_*H_ + 255)/256), 256>>>(pred_w, p_pwhi, (size_t)V_*H_);

    // embedding
    embed_kernel<<<B_*T_, 128>>>(xs, embed_w, p_xhi, p_xlo);

    // input projections: zx 2-pass, mx 3-pass
    mma_gemm<true,  false><<<dim3(FH/128, (B_*T_)/128), 256, GSMEM>>>(
        p_xhi, p_xlo, p_wxnThi, p_wxnTlo, bb, p_zx, B_*T_, FH, E_);
    mma_gemm<false, true ><<<dim3(H_/128, (B_*T_)/128), 256, GSMEM>>>(
        p_xhi, p_xlo, p_wmxnThi, p_wmxnTlo, (const float*)nullptr, p_mx, B_*T_, H_, E_);

    // recurrence (hi-only state + weights, 1-pass phases)
    reset_bar_kernel<<<1, 1>>>();
    recur_kernel<<<NBLK, 256, RS_BYTES>>>(
        p_zx, p_mx, p_wmhnT, p_whnT, p_hshi);

    // fused logits (1-pass bf16) + softmax partials + loss
    logits_nll_kernel<<<dim3(NCB, (B_*T_)/128), 256, GSMEM>>>(
        p_hshi, p_pwhi, pred_b, ys);
    nll_reduce_kernel<<<(B_*T_)/256, 256>>>(p_rownll);
    mean_kernel<<<1, 256>>>(p_rownll, out);
}

// round 17
// speedup vs baseline: 1.6408x; 1.0700x over previous
#include <cuda_runtime.h>
#include <cuda_bf16.h>
#include <cstdint>

#define B_  16
#define T_  512
#define V_  8192
#define E_  512
#define H_  1024
#define FH  4096
#define NBLK 128
#define NCB (V_/128)        // 64 column-blocks for logits

// ---------------- device scratch ----------------
__device__ __nv_bfloat16 d_xhi[B_*T_*E_];
__device__ __nv_bfloat16 d_wxnThi[(size_t)FH*E_];
__device__ __nv_bfloat16 d_wmxnThi[H_*E_];
__device__ __nv_bfloat16 d_pwhi[(size_t)V_*H_];
__device__ __nv_bfloat16 d_hshi[B_*T_*H_];
__device__ float d_whnT[(size_t)FH*H_];
__device__ float d_wmhnT[H_*H_];
__device__ float d_nwx[FH], d_nwh[FH], d_nwmx[H_], d_nwmh[H_];
__device__ float d_zx[(size_t)B_*T_*FH];
__device__ float d_mx[B_*T_*H_];
__device__ __nv_bfloat16 d_hhi[B_*H_];
__device__ __nv_bfloat16 d_mthi[B_*H_];
__device__ float d_pmax[(size_t)B_*T_*NCB];
__device__ float d_psum[(size_t)B_*T_*NCB];
__device__ float d_tlogit[B_*T_];
__device__ float d_rownll[B_*T_];
__device__ unsigned g_barcnt;

// ---------------- helpers ----------------
__device__ __forceinline__ uint32_t smem_u32(const void* p) {
    uint32_t a;
    asm("{ .reg .u64 t; cvta.to.shared.u64 t, %1; cvt.u32.u64 %0, t; }" : "=r"(a) : "l"(p));
    return a;
}
__device__ __forceinline__ void ldm_x4(uint32_t* r, uint32_t addr) {
    asm volatile("ldmatrix.sync.aligned.m8n8.x4.shared.b16 {%0,%1,%2,%3}, [%4];"
                 : "=r"(r[0]), "=r"(r[1]), "=r"(r[2]), "=r"(r[3]) : "r"(addr));
}
__device__ __forceinline__ void ldm_x2(uint32_t* r, uint32_t addr) {
    asm volatile("ldmatrix.sync.aligned.m8n8.x2.shared.b16 {%0,%1}, [%2];"
                 : "=r"(r[0]), "=r"(r[1]) : "r"(addr));
}
__device__ __forceinline__ void mma_bf16(float* c, const uint32_t* a, const uint32_t* b) {
    asm volatile("mma.sync.aligned.m16n8k16.row.col.f32.bf16.bf16.f32 "
                 "{%0,%1,%2,%3}, {%4,%5,%6,%7}, {%8,%9}, {%0,%1,%2,%3};"
                 : "+f"(c[0]), "+f"(c[1]), "+f"(c[2]), "+f"(c[3])
                 : "r"(a[0]), "r"(a[1]), "r"(a[2]), "r"(a[3]), "r"(b[0]), "r"(b[1]));
}
__device__ __forceinline__ uint32_t pk(__nv_bfloat16 a, __nv_bfloat16 b) {
    __nv_bfloat162 t = __halves2bfloat162(a, b);
    return *(uint32_t*)&t;
}
__device__ __forceinline__ void cpa16(uint32_t saddr, const void* g) {
    asm volatile("cp.async.cg.shared.global [%0], [%1], 16;" :: "r"(saddr), "l"(g) : "memory");
}

// ---------------- weight norm ----------------
__global__ void zero_norms_kernel() {
    int i = blockIdx.x * 256 + threadIdx.x;
    if (i < FH) { d_nwx[i] = 0.f; d_nwh[i] = 0.f; }
    if (i < H_) { d_nwmx[i] = 0.f; d_nwmh[i] = 0.f; }
}
__global__ void sumsq4_kernel(const float* __restrict__ wx, const float* __restrict__ wh,
                              const float* __restrict__ wmx, const float* __restrict__ wmh) {
    int id = blockIdx.y;
    const float* w; float* nrm; int K, N;
    if (id == 0)      { w = wx;  nrm = d_nwx;  K = E_; N = FH; }
    else if (id == 1) { w = wh;  nrm = d_nwh;  K = H_; N = FH; }
    else if (id == 2) { w = wmx; nrm = d_nwmx; K = E_; N = H_; }
    else              { w = wmh; nrm = d_nwmh; K = H_; N = H_; }
    int j = blockIdx.x * 256 + threadIdx.x;
    int k0 = blockIdx.z * 32;
    if (j >= N || k0 >= K) return;
    float ss = 0.f;
    #pragma unroll 4
    for (int k = k0; k < k0 + 32; k++) { float v = w[(size_t)k*N + j]; ss += v*v; }
    atomicAdd(&nrm[j], ss);
}
__global__ void scaleT_kernel(const float* __restrict__ w, const float* __restrict__ g,
                              const float* __restrict__ nrm, float* __restrict__ out,
                              int K, int N) {
    __shared__ float tile[32][33];
    int n0 = blockIdx.x * 32, k0 = blockIdx.y * 32;
    int tx = threadIdx.x, ty = threadIdx.y;
    for (int r = ty; r < 32; r += 8)
        tile[r][tx] = w[(size_t)(k0 + r)*N + n0 + tx];
    __syncthreads();
    for (int r = ty; r < 32; r += 8) {
        int n = n0 + r;
        float s = g[n] / fmaxf(sqrtf(nrm[n]), 1e-12f);
        out[(size_t)n*K + k0 + tx] = tile[tx][r] * s;
    }
}
// hi-only transposed normalize
__global__ void scaleT_bf16hi_kernel(const float* __restrict__ w, const float* __restrict__ g,
                                     const float* __restrict__ nrm,
                                     __nv_bfloat16* __restrict__ ohi,
                                     int K, int N) {
    __shared__ float tile[32][33];
    int n0 = blockIdx.x * 32, k0 = blockIdx.y * 32;
    int tx = threadIdx.x, ty = threadIdx.y;
    for (int r = ty; r < 32; r += 8)
        tile[r][tx] = w[(size_t)(k0 + r)*N + n0 + tx];
    __syncthreads();
    for (int r = ty; r < 32; r += 8) {
        int n = n0 + r;
        float s = g[n] / fmaxf(sqrtf(nrm[n]), 1e-12f);
        ohi[(size_t)n*K + k0 + tx] = __float2bfloat16(tile[tx][r] * s);
    }
}
__global__ void split_hi_kernel(const float* __restrict__ w,
                                __nv_bfloat16* __restrict__ ohi, size_t total) {
    size_t i = (size_t)blockIdx.x * 256 + threadIdx.x;
    if (i >= total) return;
    ohi[i] = __float2bfloat16(w[i]);
}

// ---------------- embedding (hi only) ----------------
__global__ void embed_kernel(const int* __restrict__ xs, const float* __restrict__ ew,
                             __nv_bfloat16* __restrict__ xhi) {
    int r = blockIdx.x;
    int idx = xs[r];
    const float4* src = (const float4*)(ew + (size_t)idx * E_);
    float4 v = src[threadIdx.x];
    if (idx == 0) v = make_float4(0.f, 0.f, 0.f, 0.f);
    size_t base = (size_t)r * E_ + threadIdx.x * 4;
    xhi[base + 0] = __float2bfloat16(v.x);
    xhi[base + 1] = __float2bfloat16(v.y);
    xhi[base + 2] = __float2bfloat16(v.z);
    xhi[base + 3] = __float2bfloat16(v.w);
}

// ---------------- 1-pass bf16 GEMM core ----------------
#define GSMEM1 65536
#define LSMEM  67584   // logits: max(gemm 64KB, epilogue 128*132*4)

__device__ __forceinline__ void gemm_main1(
    char* smem, uint32_t sbase,
    const __nv_bfloat16* Ahi, const __nv_bfloat16* Bhi,
    int bm, int bn, int K, float acc[4][4][4])
{
    const int tid = threadIdx.x, lid = tid & 31, wid = tid >> 5;
    const int wm = (wid & 1) * 64, wn = (wid >> 1) * 32;
    #pragma unroll
    for (int mt = 0; mt < 4; mt++)
        #pragma unroll
        for (int nt = 0; nt < 4; nt++)
            #pragma unroll
            for (int u = 0; u < 4; u++) acc[mt][nt][u] = 0.f;

    auto issue = [&](int ch, int buf) {
        int k0 = ch << 6;
        #pragma unroll
        for (int p = 0; p < 8; p++) {
            int i = tid + p * 256;
            int tile = i >> 10, j = i & 1023;
            int row = j >> 3, c = j & 7;
            const __nv_bfloat16* src = (tile == 0) ? Ahi : Bhi;
            int grow = ((tile == 0) ? bm : bn) + row;
            uint32_t sa = sbase + (uint32_t)buf*32768 + tile*16384
                        + (row * 8 + (c ^ (row & 7))) * 16;
            cpa16(sa, src + (size_t)grow * K + k0 + c * 8);
        }
        asm volatile("cp.async.commit_group;" ::: "memory");
    };

    const int nchunk = K >> 6;
    issue(0, 0);
    for (int ch = 0; ch < nchunk; ch++) {
        if (ch + 1 < nchunk) {
            issue(ch + 1, (ch + 1) & 1);
            asm volatile("cp.async.wait_group 1;" ::: "memory");
        } else {
            asm volatile("cp.async.wait_group 0;" ::: "memory");
        }
        __syncthreads();
        const uint32_t boff = sbase + (uint32_t)((ch & 1) * 32768);
        #pragma unroll
        for (int ks = 0; ks < 4; ks++) {
            uint32_t bh[4][2];
            {
                int row = wn + (lid & 7);
                int cc = 2 * ks + ((lid >> 3) & 1);
                #pragma unroll
                for (int nt = 0; nt < 4; nt++) {
                    int r = row + nt * 8;
                    ldm_x2(bh[nt], boff + 16384 + (r * 8 + (cc ^ (r & 7))) * 16);
                }
            }
            #pragma unroll
            for (int mt = 0; mt < 4; mt++) {
                int r = wm + mt * 16 + (lid & 7) + ((lid >> 3) & 1) * 8;
                int cc = 2 * ks + (lid >> 4);
                uint32_t ah[4];
                ldm_x4(ah, boff + (r * 8 + (cc ^ (r & 7))) * 16);
                #pragma unroll
                for (int nt = 0; nt < 4; nt++)
                    mma_bf16(acc[mt][nt], ah, bh[nt]);
            }
        }
        __syncthreads();
    }
}

template<bool BIAS>
__global__ void __launch_bounds__(256) mma_gemm1(
    const __nv_bfloat16* __restrict__ Ahi, const __nv_bfloat16* __restrict__ Bhi,
    const float* __restrict__ bias, float* __restrict__ C,
    int M, int N, int K)
{
    extern __shared__ char smem[];
    const uint32_t sbase = smem_u32(smem);
    const int tid = threadIdx.x, lid = tid & 31, wid = tid >> 5;
    const int wm = (wid & 1) * 64, wn = (wid >> 1) * 32;
    const int bn = blockIdx.x * 128, bm = blockIdx.y * 128;
    float acc[4][4][4];
    gemm_main1(smem, sbase, Ahi, Bhi, bm, bn, K, acc);

    const int mrow = (lid >> 2), ncol = (lid & 3) * 2;
    #pragma unroll
    for (int mt = 0; mt < 4; mt++) {
        #pragma unroll
        for (int nt = 0; nt < 4; nt++) {
            int row0 = bm + wm + mt * 16 + mrow;
            int col = bn + wn + nt * 8 + ncol;
            float2 v0 = make_float2(acc[mt][nt][0], acc[mt][nt][1]);
            float2 v1 = make_float2(acc[mt][nt][2], acc[mt][nt][3]);
            if (BIAS) {
                float b0 = bias[col], b1 = bias[col + 1];
                v0.x += b0; v0.y += b1;
                v1.x += b0; v1.y += b1;
            }
            *(float2*)&C[(size_t)row0 * N + col] = v0;
            *(float2*)&C[(size_t)(row0 + 8) * N + col] = v1;
        }
    }
}

// ---------------- fused logits (1-pass bf16) + online-softmax partials ----------------
__global__ void __launch_bounds__(256) logits_nll_kernel(
    const __nv_bfloat16* __restrict__ Ahi,
    const __nv_bfloat16* __restrict__ Bhi,
    const float* __restrict__ bias, const int* __restrict__ ys)
{
    extern __shared__ char smem[];
    const uint32_t sbase = smem_u32(smem);
    const int tid = threadIdx.x, lid = tid & 31, wid = tid >> 5;
    const int wm = (wid & 1) * 64, wn = (wid >> 1) * 32;
    const int bn = blockIdx.x * 128, bm = blockIdx.y * 128;
    float acc[4][4][4];
    gemm_main1(smem, sbase, Ahi, Bhi, bm, bn, H_, acc);

    float* smc = (float*)smem;
    const int mrow = (lid >> 2), ncol = (lid & 3) * 2;
    #pragma unroll
    for (int mt = 0; mt < 4; mt++) {
        #pragma unroll
        for (int nt = 0; nt < 4; nt++) {
            int r = wm + mt * 16 + mrow;
            int c = wn + nt * 8 + ncol;
            float b0 = bias[bn + c], b1 = bias[bn + c + 1];
            smc[r * 132 + c]             = acc[mt][nt][0] + b0;
            smc[r * 132 + c + 1]         = acc[mt][nt][1] + b1;
            smc[(r + 8) * 132 + c]       = acc[mt][nt][2] + b0;
            smc[(r + 8) * 132 + c + 1]   = acc[mt][nt][3] + b1;
        }
    }
    __syncthreads();

    int row = tid >> 1, half = tid & 1;
    const float* lr = smc + row * 132 + half * 64;
    float m = -3.4e38f, s = 0.f;
    #pragma unroll 8
    for (int c = 0; c < 64; c++) {
        float x = lr[c];
        float nm = fmaxf(m, x);
        s = s * __expf(m - nm) + __expf(x - nm);
        m = nm;
    }
    float m2 = __shfl_xor_sync(0xFFFFFFFF, m, 1);
    float s2 = __shfl_xor_sync(0xFFFFFFFF, s, 1);
    float M = fmaxf(m, m2);
    float S = s * __expf(m - M) + s2 * __expf(m2 - M);
    int grow = bm + row;
    if (half == 0) {
        d_pmax[(size_t)grow * NCB + blockIdx.x] = M;
        d_psum[(size_t)grow * NCB + blockIdx.x] = S;
        int target = ys[grow];
        if (target >= bn && target < bn + 128)
            d_tlogit[grow] = smc[row * 132 + (target - bn)];
    }
}

__global__ void nll_reduce_kernel(float* __restrict__ rownll) {
    int row = blockIdx.x * 256 + threadIdx.x;
    const float* pm = d_pmax + (size_t)row * NCB;
    const float* ps = d_psum + (size_t)row * NCB;
    float m = -3.4e38f, s = 0.f;
    #pragma unroll 8
    for (int c = 0; c < NCB; c++) {
        float m2 = pm[c], s2 = ps[c];
        float M = fmaxf(m, m2);
        s = s * __expf(m - M) + s2 * __expf(m2 - M);
        m = M;
    }
    rownll[row] = -(d_tlogit[row] - m - logf(s));
}

__global__ void mean_kernel(const float* __restrict__ rownll, float* __restrict__ out) {
    __shared__ float sred[256];
    int tid = threadIdx.x;
    float s = 0.f;
    for (int i = tid; i < B_*T_; i += 256) s += rownll[i];
    sred[tid] = s; __syncthreads();
    for (int k = 128; k > 0; k >>= 1) {
        if (tid < k) sred[tid] += sred[tid + k];
        __syncthreads();
    }
    if (tid == 0) out[0] = sred[0] / (float)(B_*T_);
}

// ---------------- persistent recurrence (R16-proven, unchanged) ----------------
__global__ void reset_bar_kernel() { g_barcnt = 0u; }

__device__ __forceinline__ void gbar(unsigned target) {
    __syncthreads();
    if (threadIdx.x == 0) {
        asm volatile("red.release.gpu.global.add.u32 [%0], %1;"
                     :: "l"(&g_barcnt), "r"(1u) : "memory");
        unsigned v;
        do {
            asm volatile("ld.acquire.gpu.global.u32 %0, [%1];"
                         : "=r"(v) : "l"(&g_barcnt) : "memory");
        } while (v < target);
    }
    __syncthreads();
}

#define S_WBHI  0
#define S_WAHI  65536
#define S_STG   81920
#define RS_BYTES 122880

__global__ void __launch_bounds__(256) recur_kernel(
    const float* __restrict__ zx, const float* __restrict__ mxp,
    const float* __restrict__ wmhnT, const float* __restrict__ whnT,
    __nv_bfloat16* __restrict__ hshi)
{
    extern __shared__ char smc[];
    float* stg = (float*)(smc + S_STG);
    const uint32_t sbase = smem_u32(smc);
    const int bk = blockIdx.x, tid = threadIdx.x;

    #pragma unroll 4
    for (int p = 0; p < 32; p++) {
        int col = (p >> 3) * H_ + bk * 8 + (p & 7);
        float4 v = ((const float4*)(whnT + (size_t)col * H_))[tid];
        uint32_t off = p * 2048 + ((tid * 8) ^ ((p & 7) * 16));
        *(uint2*)(smc + S_WBHI + off) = make_uint2(
            pk(__float2bfloat16(v.x), __float2bfloat16(v.y)),
            pk(__float2bfloat16(v.z), __float2bfloat16(v.w)));
    }
    #pragma unroll
    for (int p = 0; p < 8; p++) {
        int col = bk * 8 + p;
        float4 v = ((const float4*)(wmhnT + (size_t)col * H_))[tid];
        uint32_t off = p * 2048 + ((tid * 8) ^ (p * 16));
        *(uint2*)(smc + S_WAHI + off) = make_uint2(
            pk(__float2bfloat16(v.x), __float2bfloat16(v.y)),
            pk(__float2bfloat16(v.z), __float2bfloat16(v.w)));
    }
    if (tid < 128) {
        int b = tid >> 3, col = bk*8 + (tid & 7);
        ((short*)d_hhi)[b*H_ + col] = 0;
    }
    unsigned tgt = NBLK;
    gbar(tgt); tgt += NBLK;

    const int l = tid & 31, wql = tid >> 5;
    const int arow = (l & 7) + ((l >> 3) & 1) * 8;
    const uint32_t ax = (uint32_t)((arow & 7) * 16);
    const uint32_t asel = ((uint32_t)(l >> 4)) << 4;
    const int brow7 = l & 7;
    const uint32_t bx = (uint32_t)(brow7 * 16);
    const uint32_t bsel = ((uint32_t)((l >> 3) & 1)) << 4;
    int rci[2], rb[2]; size_t rzoff[2];
    #pragma unroll
    for (int o = 0; o < 2; o++) {
        int out = tid + o*256;
        rci[o] = out >> 4; rb[o] = out & 15;
        int q = rci[o] >> 3, j0 = rci[o] & 7;
        rzoff[o] = (size_t)rb[o]*T_*FH + (size_t)q*H_ + bk*8 + j0;
    }
    const int bG = tid >> 3, j0G = tid & 7;
    float creg = 0.f;

    for (int t = 0; t < T_; t++) {
        float zpre0 = __ldg(&zx[rzoff[0] + (size_t)t*FH]);
        float zpre1 = __ldg(&zx[rzoff[1] + (size_t)t*FH]);
        float mxv = 0.f;
        if (tid < 128) mxv = __ldg(&mxp[(size_t)(bG*T_ + t)*H_ + bk*8 + j0G]);

        {   // stage h (hi only: 32KB)
            #pragma unroll
            for (int p = 0; p < 8; p++) {
                int j = tid + p * 256;
                int b = j >> 7, c = j & 127;
                uint4 v = __ldcg((const uint4*)d_hhi + j);
                *(uint4*)(smc + S_STG + b*2048 + ((c*16) ^ ((b&7)*16))) = v;
            }
        }
        __syncthreads();

        // phase A (1-pass)
        float accA[4] = {0.f, 0.f, 0.f, 0.f};
        #pragma unroll
        for (int kc = 0; kc < 8; kc++) {
            uint32_t kb = (uint32_t)(wql*256 + kc*32);
            uint32_t aaddr = sbase + S_STG + (uint32_t)arow*2048 + ((kb + asel) ^ ax);
            uint32_t ah[4];
            ldm_x4(ah, aaddr);
            uint32_t bkb = (kb + bsel) ^ bx;
            uint32_t bh2[2];
            ldm_x2(bh2, sbase + S_WAHI + (uint32_t)brow7*2048 + bkb);
            mma_bf16(accA, ah, bh2);
        }
        __syncthreads();
        {
            int bq = l >> 2, cq = (l & 3) * 2;
            stg[(cq*16 + bq)*9 + wql]           = accA[0];
            stg[((cq+1)*16 + bq)*9 + wql]       = accA[1];
            stg[(cq*16 + bq + 8)*9 + wql]       = accA[2];
            stg[((cq+1)*16 + bq + 8)*9 + wql]   = accA[3];
        }
        __syncthreads();
        if (tid < 128) {
            const float* pp = stg + (j0G*16 + bG)*9;
            float s = ((pp[0]+pp[1]) + (pp[2]+pp[3])) + ((pp[4]+pp[5]) + (pp[6]+pp[7]));
            float mval = s * mxv;
            __nv_bfloat16 mh = __float2bfloat16(mval);
            __stcg((short*)&d_mthi[bG*H_ + bk*8 + j0G], *(short*)&mh);
        }
        gbar(tgt); tgt += NBLK;

        {   // stage m (hi only)
            #pragma unroll
            for (int p = 0; p < 8; p++) {
                int j = tid + p * 256;
                int b = j >> 7, c = j & 127;
                uint4 v = __ldcg((const uint4*)d_mthi + j);
                *(uint4*)(smc + S_STG + b*2048 + ((c*16) ^ ((b&7)*16))) = v;
            }
        }
        __syncthreads();

        // phase B (1-pass)
        float acc[4][4];
        #pragma unroll
        for (int nt = 0; nt < 4; nt++)
            #pragma unroll
            for (int u = 0; u < 4; u++) acc[nt][u] = 0.f;
        #pragma unroll
        for (int kc = 0; kc < 8; kc++) {
            uint32_t kb = (uint32_t)(wql*256 + kc*32);
            uint32_t aaddr = sbase + S_STG + (uint32_t)arow*2048 + ((kb + asel) ^ ax);
            uint32_t ah[4];
            ldm_x4(ah, aaddr);
            uint32_t bkb = (kb + bsel) ^ bx;
            #pragma unroll
            for (int nt = 0; nt < 4; nt++) {
                uint32_t bh[2];
                ldm_x2(bh, sbase + S_WBHI + (uint32_t)(nt*8 + brow7)*2048 + bkb);
                mma_bf16(acc[nt], ah, bh);
            }
        }
        __syncthreads();
        {
            int bq = l >> 2, cq = (l & 3) * 2;
            #pragma unroll
            for (int nt = 0; nt < 4; nt++) {
                int c0 = nt*8 + cq;
                stg[(c0*16 + bq)*9 + wql]          = acc[nt][0];
                stg[((c0+1)*16 + bq)*9 + wql]      = acc[nt][1];
                stg[(c0*16 + bq + 8)*9 + wql]      = acc[nt][2];
                stg[((c0+1)*16 + bq + 8)*9 + wql]  = acc[nt][3];
            }
        }
        __syncthreads();

        {
            const float* p0 = stg + (rci[0]*16 + rb[0])*9;
            float s0 = ((p0[0]+p0[1]) + (p0[2]+p0[3])) + ((p0[4]+p0[5]) + (p0[6]+p0[7]));
            stg[8192 + rb[0]*32 + rci[0]] = zpre0 + s0;
            const float* p1 = stg + (rci[1]*16 + rb[1])*9;
            float s1 = ((p1[0]+p1[1]) + (p1[2]+p1[3])) + ((p1[4]+p1[5]) + (p1[6]+p1[7]));
            stg[8192 + rb[1]*32 + rci[1]] = zpre1 + s1;
        }
        __syncthreads();

        if (tid < 128) {
            float zi = stg[8192 + bG*32 +      j0G];
            float zf = stg[8192 + bG*32 +  8 + j0G];
            float zo = stg[8192 + bG*32 + 16 + j0G];
            float zu = stg[8192 + bG*32 + 24 + j0G];
            float ig = 1.f / (1.f + expf(-zi));
            float fg = 1.f / (1.f + expf(-zf));
            float og = 1.f / (1.f + expf(-zo));
            float ug = tanhf(zu);
            creg = fg * creg + ig * ug;
            float h = og * tanhf(creg);
            int col = bk*8 + j0G;
            __nv_bfloat16 hh = __float2bfloat16(h);
            __stcg((short*)&d_hhi[bG*H_ + col], *(short*)&hh);
            hshi[(size_t)(bG*T_ + t)*H_ + col] = hh;
        }
        gbar(tgt); tgt += NBLK;
    }
}

// ---------------- launcher ----------------
extern "C" void kernel_launch(void* const* d_in, const int* in_sizes, int n_in,
                              void* d_out, int out_size) {
    (void)in_sizes; (void)n_in; (void)out_size;
    const int*   xs      = (const int*)  d_in[0];
    const int*   ys      = (const int*)  d_in[1];
    const float* embed_w = (const float*)d_in[2];
    const float* wx      = (const float*)d_in[3];
    const float* wh      = (const float*)d_in[4];
    const float* wmx     = (const float*)d_in[5];
    const float* wmh     = (const float*)d_in[6];
    const float* bb      = (const float*)d_in[7];
    const float* gx      = (const float*)d_in[8];
    const float* gh      = (const float*)d_in[9];
    const float* gmx     = (const float*)d_in[10];
    const float* gmh     = (const float*)d_in[11];
    const float* pred_w  = (const float*)d_in[12];
    const float* pred_b  = (const float*)d_in[13];
    float* out = (float*)d_out;

    float *p_whnT, *p_wmhnT, *p_zx, *p_mx, *p_rownll;
    float *p_nwx, *p_nwh, *p_nwmx, *p_nwmh;
    __nv_bfloat16 *p_xhi, *p_wxnThi, *p_wmxnThi, *p_pwhi, *p_hshi;
    cudaGetSymbolAddress((void**)&p_whnT,    d_whnT);
    cudaGetSymbolAddress((void**)&p_wmhnT,   d_wmhnT);
    cudaGetSymbolAddress((void**)&p_zx,      d_zx);
    cudaGetSymbolAddress((void**)&p_mx,      d_mx);
    cudaGetSymbolAddress((void**)&p_rownll,  d_rownll);
    cudaGetSymbolAddress((void**)&p_nwx,     d_nwx);
    cudaGetSymbolAddress((void**)&p_nwh,     d_nwh);
    cudaGetSymbolAddress((void**)&p_nwmx,    d_nwmx);
    cudaGetSymbolAddress((void**)&p_nwmh,    d_nwmh);
    cudaGetSymbolAddress((void**)&p_xhi,     d_xhi);
    cudaGetSymbolAddress((void**)&p_wxnThi,  d_wxnThi);
    cudaGetSymbolAddress((void**)&p_wmxnThi, d_wmxnThi);
    cudaGetSymbolAddress((void**)&p_pwhi,    d_pwhi);
    cudaGetSymbolAddress((void**)&p_hshi,    d_hshi);

    static bool attr_set = false;
    if (!attr_set) {
        cudaFuncSetAttribute(recur_kernel, cudaFuncAttributeMaxDynamicSharedMemorySize, RS_BYTES);
        cudaFuncSetAttribute(mma_gemm1<true>,  cudaFuncAttributeMaxDynamicSharedMemorySize, GSMEM1);
        cudaFuncSetAttribute(mma_gemm1<false>, cudaFuncAttributeMaxDynamicSharedMemorySize, GSMEM1);
        cudaFuncSetAttribute(logits_nll_kernel, cudaFuncAttributeMaxDynamicSharedMemorySize, LSMEM);
        attr_set = true;
    }

    // weight norm
    zero_norms_kernel<<<16, 256>>>();
    sumsq4_kernel<<<dim3(16, 4, 32), 256>>>(wx, wh, wmx, wmh);
    scaleT_bf16hi_kernel<<<dim3(FH/32, E_/32), dim3(32,8)>>>(wx,  gx,  p_nwx,  p_wxnThi,  E_, FH);
    scaleT_bf16hi_kernel<<<dim3(H_/32, E_/32), dim3(32,8)>>>(wmx, gmx, p_nwmx, p_wmxnThi, E_, H_);
    scaleT_kernel<<<dim3(FH/32, H_/32), dim3(32,8)>>>(wh,  gh,  p_nwh,  p_whnT,  H_, FH);
    scaleT_kernel<<<dim3(H_/32, H_/32), dim3(32,8)>>>(wmh, gmh, p_nwmh, p_wmhnT, H_, H_);
    split_hi_kernel<<<(int)(((size_t)V_*H_ + 255)/256), 256>>>(pred_w, p_pwhi, (size_t)V_*H_);

    // embedding (hi only)
    embed_kernel<<<B_*T_, 128>>>(xs, embed_w, p_xhi);

    // input projections: both 1-pass bf16
    mma_gemm1<true ><<<dim3(FH/128, (B_*T_)/128), 256, GSMEM1>>>(
        p_xhi, p_wxnThi, bb, p_zx, B_*T_, FH, E_);
    mma_gemm1<false><<<dim3(H_/128, (B_*T_)/128), 256, GSMEM1>>>(
        p_xhi, p_wmxnThi, (const float*)nullptr, p_mx, B_*T_, H_, E_);

    // recurrence (R16-proven)
    reset_bar_kernel<<<1, 1>>>();
    recur_kernel<<<NBLK, 256, RS_BYTES>>>(
        p_zx, p_mx, p_wmhnT, p_whnT, p_hshi);

    // fused logits (1-pass bf16) + softmax partials + loss
    logits_nll_kernel<<<dim3(NCB, (B_*T_)/128), 256, LSMEM>>>(
        p_hshi, p_pwhi, pred_b, ys);
    nll_reduce_kernel<<<(B_*T_)/256, 256>>>(p_rownll);
    mean_kernel<<<1, 256>>>(p_rownll, out);
}